// round 10
// baseline (speedup 1.0000x reference)
#include <cuda_runtime.h>
#include <cuda_fp16.h>
#include <cstdint>
#include <stdint.h>
#include <math.h>

// Problem constants (fixed by the dataset)
#define N_NODES 100000
#define N_EDGES 1600000
#define DIM 128
#define ODIM 64
#define WSLOT 16384
#define WTOT (5 * WSLOT + ODIM * DIM)
#define PADB 272   // smem row stride in bytes, multiple of 16, conflict-free
#define SCHUNK 1024

// ---------------- scratch (static device globals; no allocation) -----------
__device__ signed char g_M8a[(size_t)N_NODES * DIM]; // int8 messages ping
__device__ signed char g_M8b[(size_t)N_NODES * DIM]; // int8 messages pong
__device__ float       g_sca[N_NODES];               // per-row dequant scale ping
__device__ float       g_scb[N_NODES];               // per-row dequant scale pong
__device__ __half      g_F16[(size_t)N_NODES * DIM]; // fp16 MLP intermediate
__device__ float       g_C[(size_t)N_NODES * ODIM];  // final pre-softmax logits
__device__ int         g_deg[N_NODES];
__device__ int         g_cur[N_NODES];
__device__ int         g_off[N_NODES + 1];
__device__ int         g_csr[N_EDGES];
__device__ int         g_bsum[128];
__device__ float       g_dinv[N_NODES];
__device__ __half      g_Wf[WTOT];                   // fp16 transposed weights [N][K]

// ---------------- mma.sync fp16 helper (baseline PTX) ----------------------
__device__ __forceinline__ void mma_f16(float* c, const unsigned int* a,
                                        const unsigned int* b) {
    asm volatile(
        "mma.sync.aligned.m16n8k16.row.col.f32.f16.f16.f32 "
        "{%0,%1,%2,%3}, {%4,%5,%6,%7}, {%8,%9}, {%0,%1,%2,%3};"
        : "+f"(c[0]), "+f"(c[1]), "+f"(c[2]), "+f"(c[3])
        : "r"(a[0]), "r"(a[1]), "r"(a[2]), "r"(a[3]), "r"(b[0]), "r"(b[1]));
}

// ---------------- setup kernels --------------------------------------------
__global__ void k_zero(int n) {
    int i = blockIdx.x * blockDim.x + threadIdx.x;
    if (i < n) { g_deg[i] = 0; g_cur[i] = 0; }
}
__global__ void k_count(const int* __restrict__ dst, int e) {
    int i = blockIdx.x * blockDim.x + threadIdx.x;
    if (i < e) atomicAdd(&g_deg[dst[i]], 1);
}

// block sums for scan + dinv (deg is final here)
__global__ void k_bsum(int n) {
    __shared__ int sh[SCHUNK];
    int i = blockIdx.x * SCHUNK + threadIdx.x;
    int d = (i < n) ? g_deg[i] : 0;
    if (i < n) g_dinv[i] = rsqrtf((float)(d + 1));
    sh[threadIdx.x] = d;
    __syncthreads();
    for (int off = SCHUNK / 2; off > 0; off >>= 1) {
        if (threadIdx.x < off) sh[threadIdx.x] += sh[threadIdx.x + off];
        __syncthreads();
    }
    if (threadIdx.x == 0) g_bsum[blockIdx.x] = sh[0];
}
__global__ void k_bscan(int nb) {
    __shared__ int sh[128];
    int v = (threadIdx.x < nb) ? g_bsum[threadIdx.x] : 0;
    sh[threadIdx.x] = v;
    __syncthreads();
    for (int off = 1; off < 128; off <<= 1) {
        int t = (threadIdx.x >= off) ? sh[threadIdx.x - off] : 0;
        __syncthreads();
        sh[threadIdx.x] += t;
        __syncthreads();
    }
    if (threadIdx.x < nb) g_bsum[threadIdx.x] = sh[threadIdx.x] - v;
}
__global__ void k_offsets(int n) {
    __shared__ int sh[SCHUNK];
    int i = blockIdx.x * SCHUNK + threadIdx.x;
    int v = (i < n) ? g_deg[i] : 0;
    sh[threadIdx.x] = v;
    __syncthreads();
    for (int off = 1; off < SCHUNK; off <<= 1) {
        int t = (threadIdx.x >= off) ? sh[threadIdx.x - off] : 0;
        __syncthreads();
        sh[threadIdx.x] += t;
        __syncthreads();
    }
    int excl = g_bsum[blockIdx.x] + sh[threadIdx.x] - v;
    if (i < n) g_off[i] = excl;
    if (i == n - 1) g_off[n] = excl + v;
}
__global__ void k_fill(const int* __restrict__ src, const int* __restrict__ dst, int e) {
    int i = blockIdx.x * blockDim.x + threadIdx.x;
    if (i < e) {
        int d = dst[i];
        int pos = g_off[d] + atomicAdd(&g_cur[d], 1);
        g_csr[pos] = src[i];
    }
}

// transpose + fp16 convert ALL weights in one launch
__global__ void k_convW_all(const float* __restrict__ W0, const float* __restrict__ W1,
                            const float* __restrict__ W2, const float* __restrict__ W3,
                            const float* __restrict__ Wm1, const float* __restrict__ Wm2) {
    int i = blockIdx.x * blockDim.x + threadIdx.x;
    if (i >= WTOT) return;
    int slot = i >> 14;
    int j = i & 16383;
    const float* W;
    int N;
    switch (slot) {
        case 0:  W = W0;  N = 128; break;
        case 1:  W = W1;  N = 128; break;
        case 2:  W = W2;  N = 128; break;
        case 3:  W = W3;  N = 128; break;
        case 4:  W = Wm1; N = 128; break;
        default: W = Wm2; N = 64;  break;
    }
    const int K = 128;
    int nrow = j / K;
    int k = j % K;
    g_Wf[i] = __float2half_rn(W[k * N + nrow]);
}

// ---------------- plain fp16 HMMA GEMM (first layer + MLP2) -----------------
// acc = act(A) @ W; act = relu(a+abias) if abias. fp32 accum.
// If C8: int8 quantize w/ per-row scale Csc = M*dinv/127 (GCN message mode).
// Else:  C[row] = acc + cbias (fp32 out).
template <int BN>
__device__ __forceinline__ void gemm_body(const float* __restrict__ A32,
                                          const __half* __restrict__ A16,
                                          const float* __restrict__ abias,
                                          const __half* __restrict__ Wf,
                                          const float* __restrict__ cbias,
                                          float* __restrict__ C,
                                          signed char* __restrict__ C8,
                                          float* __restrict__ Csc,
                                          int n, char* smem)
{
    constexpr int NT = BN / 16;
    const unsigned int A_OF = 0;
    const unsigned int B_OF = 128 * PADB;

    const int tid  = threadIdx.x;
    const int wid  = tid >> 5;
    const int lane = tid & 31;
    const int wr   = wid >> 1;
    const int wc   = wid & 1;
    const int row0 = blockIdx.x * 128;

    // ---- A tile -> fp16 smem, fused relu(+abias)
    for (int i = tid; i < 128 * 16; i += 256) {
        int row = i >> 4;
        int unit = i & 15;
        int grow = row0 + row;
        uint4 u = make_uint4(0, 0, 0, 0);
        __half2* hp = (__half2*)&u;
        if (grow < n) {
            if (A16) {
                u = *(const uint4*)(A16 + (size_t)grow * 128 + unit * 8);
            } else {
                const float4* p = (const float4*)(A32 + (size_t)grow * 128 + unit * 8);
                float4 a0 = p[0], a1 = p[1];
                hp[0] = __floats2half2_rn(a0.x, a0.y);
                hp[1] = __floats2half2_rn(a0.z, a0.w);
                hp[2] = __floats2half2_rn(a1.x, a1.y);
                hp[3] = __floats2half2_rn(a1.z, a1.w);
            }
        }
        if (abias) {
            const float4* b = (const float4*)(abias + unit * 8);
            float4 b0 = b[0], b1 = b[1];
            float bb[8];
            bb[0] = b0.x; bb[1] = b0.y; bb[2] = b0.z; bb[3] = b0.w;
            bb[4] = b1.x; bb[5] = b1.y; bb[6] = b1.z; bb[7] = b1.w;
#pragma unroll
            for (int j = 0; j < 4; j++) {
                float2 f = __half22float2(hp[j]);
                f.x = fmaxf(f.x + bb[2 * j], 0.f);
                f.y = fmaxf(f.y + bb[2 * j + 1], 0.f);
                hp[j] = __floats2half2_rn(f.x, f.y);
            }
        }
        *(uint4*)(smem + A_OF + (unsigned int)row * PADB + (unsigned int)unit * 16) = u;
    }

    // ---- W tile
    for (int i = tid; i < BN * 16; i += 256) {
        int row = i >> 4;
        int unit = i & 15;
        *(uint4*)(smem + B_OF + (unsigned int)row * PADB + (unsigned int)unit * 16) =
            ((const uint4*)Wf)[row * 16 + unit];
    }
    __syncthreads();

    const int g  = lane >> 2;
    const int tg = lane & 3;
    float acc[2][NT][4];
#pragma unroll
    for (int mt = 0; mt < 2; mt++)
#pragma unroll
        for (int nt = 0; nt < NT; nt++)
#pragma unroll
            for (int j = 0; j < 4; j++) acc[mt][nt][j] = 0.f;

#pragma unroll
    for (int ks = 0; ks < 8; ks++) {
        const unsigned int kb = (unsigned int)(ks * 16 + tg * 2) * 2;
        unsigned int a[2][4];
#pragma unroll
        for (int mt = 0; mt < 2; mt++) {
            unsigned int ro = A_OF + (unsigned int)(wr * 32 + mt * 16 + g) * PADB + kb;
            a[mt][0] = *(const unsigned int*)(smem + ro);
            a[mt][1] = *(const unsigned int*)(smem + ro + 8 * PADB);
            a[mt][2] = *(const unsigned int*)(smem + ro + 16);
            a[mt][3] = *(const unsigned int*)(smem + ro + 8 * PADB + 16);
        }
#pragma unroll
        for (int nt = 0; nt < NT; nt++) {
            unsigned int no = B_OF + (unsigned int)(wc * NT * 8 + nt * 8 + g) * PADB + kb;
            unsigned int b[2];
            b[0] = *(const unsigned int*)(smem + no);
            b[1] = *(const unsigned int*)(smem + no + 16);
#pragma unroll
            for (int mt = 0; mt < 2; mt++)
                mma_f16(acc[mt][nt], a[mt], b);
        }
    }

    if (C8) {
        __syncthreads();
        float* rmax = (float*)smem;
        if (tid < 128) rmax[tid] = 0.f;
        __syncthreads();
#pragma unroll
        for (int mt = 0; mt < 2; mt++) {
            int lr = wr * 32 + mt * 16 + g;
            float m0 = 0.f, m1 = 0.f;
#pragma unroll
            for (int nt = 0; nt < NT; nt++) {
                m0 = fmaxf(m0, fmaxf(fabsf(acc[mt][nt][0]), fabsf(acc[mt][nt][1])));
                m1 = fmaxf(m1, fmaxf(fabsf(acc[mt][nt][2]), fabsf(acc[mt][nt][3])));
            }
            atomicMax((int*)&rmax[lr], __float_as_int(m0));
            atomicMax((int*)&rmax[lr + 8], __float_as_int(m1));
        }
        __syncthreads();
#pragma unroll
        for (int mt = 0; mt < 2; mt++) {
            int lr = wr * 32 + mt * 16 + g;
            int grow = row0 + lr;
            float M0 = rmax[lr], M1 = rmax[lr + 8];
            float q0 = (M0 > 0.f) ? 127.f / M0 : 0.f;
            float q1 = (M1 > 0.f) ? 127.f / M1 : 0.f;
            if (wc == 0 && tg == 0) {
                if (grow < n)     Csc[grow]     = M0 * g_dinv[grow] * (1.f / 127.f);
                if (grow + 8 < n) Csc[grow + 8] = M1 * g_dinv[grow + 8] * (1.f / 127.f);
            }
#pragma unroll
            for (int nt = 0; nt < NT; nt++) {
                int col = wc * NT * 8 + nt * 8 + tg * 2;
                if (grow < n) {
                    int b0 = __float2int_rn(acc[mt][nt][0] * q0);
                    int b1 = __float2int_rn(acc[mt][nt][1] * q0);
                    *(unsigned short*)(C8 + (size_t)grow * 128 + col) =
                        (unsigned short)(((b1 & 0xff) << 8) | (b0 & 0xff));
                }
                if (grow + 8 < n) {
                    int b2 = __float2int_rn(acc[mt][nt][2] * q1);
                    int b3 = __float2int_rn(acc[mt][nt][3] * q1);
                    *(unsigned short*)(C8 + (size_t)(grow + 8) * 128 + col) =
                        (unsigned short)(((b3 & 0xff) << 8) | (b2 & 0xff));
                }
            }
        }
    } else {
#pragma unroll
        for (int mt = 0; mt < 2; mt++) {
            int r0i = row0 + wr * 32 + mt * 16 + g;
#pragma unroll
            for (int nt = 0; nt < NT; nt++) {
                int col = wc * NT * 8 + nt * 8 + tg * 2;
                float c0 = acc[mt][nt][0], c1 = acc[mt][nt][1];
                float c2 = acc[mt][nt][2], c3 = acc[mt][nt][3];
                if (cbias) {
                    float b0 = cbias[col], b1 = cbias[col + 1];
                    c0 += b0; c1 += b1; c2 += b0; c3 += b1;
                }
                if (r0i < n)
                    *(float2*)(C + (size_t)r0i * BN + col) = make_float2(c0, c1);
                if (r0i + 8 < n)
                    *(float2*)(C + (size_t)(r0i + 8) * BN + col) = make_float2(c2, c3);
            }
        }
    }
}

__global__ void __launch_bounds__(256, 2)
k_gemm128(const float* A32, const __half* A16, const float* abias,
          const __half* Wf, const float* cbias,
          float* C, signed char* C8, float* Csc, int n)
{
    extern __shared__ __align__(16) char smem_dyn[];
    gemm_body<128>(A32, A16, abias, Wf, cbias, C, C8, Csc, n, smem_dyn);
}

__global__ void __launch_bounds__(256, 2)
k_gemm64(const float* A32, const __half* A16, const float* abias,
         const __half* Wf, const float* cbias,
         float* C, signed char* C8, float* Csc, int n)
{
    extern __shared__ __align__(16) char smem_dyn[];
    gemm_body<64>(A32, A16, abias, Wf, cbias, C, C8, Csc, n, smem_dyn);
}

// ---------------- fused gather + GEMM (GCN layers 1-3 + MLP1) ---------------
// Per 128-row tile: A[r] = relu( dinv[r]*sum_{s in N(r)+self} sc[s]*M8in[s] + abias )
// then acc = A @ W (fp16 MMA).
// If C8: int8 quantize (message out). Else: C16 = half(acc + cbias) (MLP out).
#define ACC4(u, f)                                            \
    do {                                                      \
        a0 = fmaf((f), (float)(signed char)((u)), a0);        \
        a1 = fmaf((f), (float)(signed char)((u) >> 8), a1);   \
        a2 = fmaf((f), (float)(signed char)((u) >> 16), a2);  \
        a3 = fmaf((f), (float)(signed char)((u) >> 24), a3);  \
    } while (0)

__global__ void __launch_bounds__(256, 2)
k_gg(const unsigned int* __restrict__ M8in, const float* __restrict__ scin,
     const float* __restrict__ abias, const __half* __restrict__ Wf,
     const float* __restrict__ cbias,
     signed char* __restrict__ C8, float* __restrict__ Csc,
     __half* __restrict__ C16, int n)
{
    extern __shared__ __align__(16) char smem[];
    const unsigned int A_OF = 0;
    const unsigned int B_OF = 128 * PADB;
    const int tid  = threadIdx.x;
    const int wid  = tid >> 5;
    const int lane = tid & 31;
    const int wr   = wid >> 1;
    const int wc   = wid & 1;
    const int row0 = blockIdx.x * 128;

    // ---- W tile (all warps, issued first so loads overlap gather)
    for (int i = tid; i < 128 * 16; i += 256) {
        int row = i >> 4;
        int unit = i & 15;
        *(uint4*)(smem + B_OF + (unsigned int)row * PADB + (unsigned int)unit * 16) =
            ((const uint4*)Wf)[row * 16 + unit];
    }

    // ---- gather phase: warp w fills rows w*16 .. w*16+15
    const float4 bb = *(const float4*)(abias + lane * 4);
    for (int rr = 0; rr < 16; rr++) {
        int r = wid * 16 + rr;
        int grow = row0 + r;
        float a0 = 0.f, a1 = 0.f, a2 = 0.f, a3 = 0.f;
        uint2 outv = make_uint2(0, 0);
        if (grow < n) {
            int beg = g_off[grow];
            int total = g_off[grow + 1] - beg + 1;   // +1 = self loop first
            for (int base = 0; base < total; base += 32) {
                int cnt = total - base;
                if (cnt > 32) cnt = 32;
                int vj = base + lane;
                int idx = 0;
                float scv = 0.f;
                if (lane < cnt) {
                    idx = (vj == 0) ? grow : g_csr[beg + vj - 1];
                    scv = scin[idx];
                }
                int j = 0;
                for (; j + 4 <= cnt; j += 4) {
                    int s0 = __shfl_sync(0xFFFFFFFFu, idx, j);
                    int s1 = __shfl_sync(0xFFFFFFFFu, idx, j + 1);
                    int s2 = __shfl_sync(0xFFFFFFFFu, idx, j + 2);
                    int s3 = __shfl_sync(0xFFFFFFFFu, idx, j + 3);
                    float f0 = __shfl_sync(0xFFFFFFFFu, scv, j);
                    float f1 = __shfl_sync(0xFFFFFFFFu, scv, j + 1);
                    float f2 = __shfl_sync(0xFFFFFFFFu, scv, j + 2);
                    float f3 = __shfl_sync(0xFFFFFFFFu, scv, j + 3);
                    unsigned int u0 = M8in[(size_t)s0 * 32 + lane];
                    unsigned int u1 = M8in[(size_t)s1 * 32 + lane];
                    unsigned int u2 = M8in[(size_t)s2 * 32 + lane];
                    unsigned int u3 = M8in[(size_t)s3 * 32 + lane];
                    ACC4(u0, f0);
                    ACC4(u1, f1);
                    ACC4(u2, f2);
                    ACC4(u3, f3);
                }
                for (; j < cnt; j++) {
                    int s = __shfl_sync(0xFFFFFFFFu, idx, j);
                    float f = __shfl_sync(0xFFFFFFFFu, scv, j);
                    unsigned int u = M8in[(size_t)s * 32 + lane];
                    ACC4(u, f);
                }
            }
            float di = g_dinv[grow];
            a0 = fmaxf(fmaf(a0, di, bb.x), 0.f);
            a1 = fmaxf(fmaf(a1, di, bb.y), 0.f);
            a2 = fmaxf(fmaf(a2, di, bb.z), 0.f);
            a3 = fmaxf(fmaf(a3, di, bb.w), 0.f);
            __half2 h01 = __floats2half2_rn(a0, a1);
            __half2 h23 = __floats2half2_rn(a2, a3);
            outv.x = *(unsigned int*)&h01;
            outv.y = *(unsigned int*)&h23;
        }
        *(uint2*)(smem + A_OF + (unsigned int)r * PADB + (unsigned int)lane * 8) = outv;
    }
    __syncthreads();

    // ---- MMA phase (BN = 128)
    const int g  = lane >> 2;
    const int tg = lane & 3;
    float acc[2][8][4];
#pragma unroll
    for (int mt = 0; mt < 2; mt++)
#pragma unroll
        for (int nt = 0; nt < 8; nt++)
#pragma unroll
            for (int j = 0; j < 4; j++) acc[mt][nt][j] = 0.f;

#pragma unroll
    for (int ks = 0; ks < 8; ks++) {
        const unsigned int kb = (unsigned int)(ks * 16 + tg * 2) * 2;
        unsigned int a[2][4];
#pragma unroll
        for (int mt = 0; mt < 2; mt++) {
            unsigned int ro = A_OF + (unsigned int)(wr * 32 + mt * 16 + g) * PADB + kb;
            a[mt][0] = *(const unsigned int*)(smem + ro);
            a[mt][1] = *(const unsigned int*)(smem + ro + 8 * PADB);
            a[mt][2] = *(const unsigned int*)(smem + ro + 16);
            a[mt][3] = *(const unsigned int*)(smem + ro + 8 * PADB + 16);
        }
#pragma unroll
        for (int nt = 0; nt < 8; nt++) {
            unsigned int no = B_OF + (unsigned int)(wc * 64 + nt * 8 + g) * PADB + kb;
            unsigned int b[2];
            b[0] = *(const unsigned int*)(smem + no);
            b[1] = *(const unsigned int*)(smem + no + 16);
#pragma unroll
            for (int mt = 0; mt < 2; mt++)
                mma_f16(acc[mt][nt], a[mt], b);
        }
    }

    // ---- epilogue
    if (C8) {
        __syncthreads();
        float* rmax = (float*)smem;
        if (tid < 128) rmax[tid] = 0.f;
        __syncthreads();
#pragma unroll
        for (int mt = 0; mt < 2; mt++) {
            int lr = wr * 32 + mt * 16 + g;
            float m0 = 0.f, m1 = 0.f;
#pragma unroll
            for (int nt = 0; nt < 8; nt++) {
                m0 = fmaxf(m0, fmaxf(fabsf(acc[mt][nt][0]), fabsf(acc[mt][nt][1])));
                m1 = fmaxf(m1, fmaxf(fabsf(acc[mt][nt][2]), fabsf(acc[mt][nt][3])));
            }
            atomicMax((int*)&rmax[lr], __float_as_int(m0));
            atomicMax((int*)&rmax[lr + 8], __float_as_int(m1));
        }
        __syncthreads();
#pragma unroll
        for (int mt = 0; mt < 2; mt++) {
            int lr = wr * 32 + mt * 16 + g;
            int grow = row0 + lr;
            float M0 = rmax[lr], M1 = rmax[lr + 8];
            float q0 = (M0 > 0.f) ? 127.f / M0 : 0.f;
            float q1 = (M1 > 0.f) ? 127.f / M1 : 0.f;
            if (wc == 0 && tg == 0) {
                if (grow < n)     Csc[grow]     = M0 * g_dinv[grow] * (1.f / 127.f);
                if (grow + 8 < n) Csc[grow + 8] = M1 * g_dinv[grow + 8] * (1.f / 127.f);
            }
#pragma unroll
            for (int nt = 0; nt < 8; nt++) {
                int col = wc * 64 + nt * 8 + tg * 2;
                if (grow < n) {
                    int b0 = __float2int_rn(acc[mt][nt][0] * q0);
                    int b1 = __float2int_rn(acc[mt][nt][1] * q0);
                    *(unsigned short*)(C8 + (size_t)grow * 128 + col) =
                        (unsigned short)(((b1 & 0xff) << 8) | (b0 & 0xff));
                }
                if (grow + 8 < n) {
                    int b2 = __float2int_rn(acc[mt][nt][2] * q1);
                    int b3 = __float2int_rn(acc[mt][nt][3] * q1);
                    *(unsigned short*)(C8 + (size_t)(grow + 8) * 128 + col) =
                        (unsigned short)(((b3 & 0xff) << 8) | (b2 & 0xff));
                }
            }
        }
    } else {
#pragma unroll
        for (int mt = 0; mt < 2; mt++) {
            int r0i = row0 + wr * 32 + mt * 16 + g;
#pragma unroll
            for (int nt = 0; nt < 8; nt++) {
                int col = wc * 64 + nt * 8 + tg * 2;
                float b0 = cbias[col], b1 = cbias[col + 1];
                if (r0i < n) {
                    __half2 h = __floats2half2_rn(acc[mt][nt][0] + b0, acc[mt][nt][1] + b1);
                    *(__half2*)(C16 + (size_t)r0i * 128 + col) = h;
                }
                if (r0i + 8 < n) {
                    __half2 h = __floats2half2_rn(acc[mt][nt][2] + b0, acc[mt][nt][3] + b1);
                    *(__half2*)(C16 + (size_t)(r0i + 8) * 128 + col) = h;
                }
            }
        }
    }
}

// ---------------- log_softmax over 64 cols, one warp per row ---------------
__launch_bounds__(256)
__global__ void k_logsoftmax(const float* __restrict__ X,
                             float* __restrict__ out, int n)
{
    int warp = (blockIdx.x * blockDim.x + threadIdx.x) >> 5;
    int lane = threadIdx.x & 31;
    if (warp >= n) return;
    const float* row = X + (size_t)warp * 64;
    float v0 = row[lane];
    float v1 = row[lane + 32];
    float m = fmaxf(v0, v1);
#pragma unroll
    for (int o = 16; o > 0; o >>= 1) m = fmaxf(m, __shfl_xor_sync(0xFFFFFFFFu, m, o));
    float s = expf(v0 - m) + expf(v1 - m);
#pragma unroll
    for (int o = 16; o > 0; o >>= 1) s += __shfl_xor_sync(0xFFFFFFFFu, s, o);
    float lg = m + logf(s);
    float* orow = out + (size_t)warp * 64;
    orow[lane]      = v0 - lg;
    orow[lane + 32] = v1 - lg;
}

// ---------------- host launcher ---------------------------------------------
extern "C" void kernel_launch(void* const* d_in, const int* in_sizes, int n_in,
                              void* d_out, int out_size)
{
    const float* x   = (const float*)d_in[0];
    const int*   ei  = (const int*)d_in[1];
    const float* W0  = (const float*)d_in[2];
    const float* b0  = (const float*)d_in[3];
    const float* W1  = (const float*)d_in[4];
    const float* b1  = (const float*)d_in[5];
    const float* W2  = (const float*)d_in[6];
    const float* b2  = (const float*)d_in[7];
    const float* W3  = (const float*)d_in[8];
    const float* b3  = (const float*)d_in[9];
    const float* Wm1 = (const float*)d_in[10];
    const float* bm1 = (const float*)d_in[11];
    const float* Wm2 = (const float*)d_in[12];
    const float* bm2 = (const float*)d_in[13];
    float* out = (float*)d_out;

    const int n = in_sizes[0] / DIM;      // 100000
    const int e = in_sizes[1] / 2;        // 1600000
    const int* src = ei;
    const int* dst = ei + e;

    signed char* M8a = 0;
    signed char* M8b = 0;
    float* Sca = 0;
    float* Scb = 0;
    __half* F16 = 0;
    float* Cb = 0;
    __half* Wf = 0;
    cudaGetSymbolAddress((void**)&M8a, g_M8a);
    cudaGetSymbolAddress((void**)&M8b, g_M8b);
    cudaGetSymbolAddress((void**)&Sca, g_sca);
    cudaGetSymbolAddress((void**)&Scb, g_scb);
    cudaGetSymbolAddress((void**)&F16, g_F16);
    cudaGetSymbolAddress((void**)&Cb,  g_C);
    cudaGetSymbolAddress((void**)&Wf,  g_Wf);

    const int SM128 = 128 * PADB + 128 * PADB;   // 69632
    const int SM64  = 128 * PADB + 64 * PADB;    // 52224
    cudaFuncSetAttribute(k_gemm128, cudaFuncAttributeMaxDynamicSharedMemorySize, SM128);
    cudaFuncSetAttribute(k_gemm64,  cudaFuncAttributeMaxDynamicSharedMemorySize, SM64);
    cudaFuncSetAttribute(k_gg,      cudaFuncAttributeMaxDynamicSharedMemorySize, SM128);

    const int nscanb = (n + SCHUNK - 1) / SCHUNK;

    // ---- setup: degrees, CSR, dinv, weights ----
    k_zero<<<(n + 255) / 256, 256>>>(n);
    k_count<<<(e + 255) / 256, 256>>>(dst, e);
    k_bsum<<<nscanb, SCHUNK>>>(n);           // also computes dinv
    k_bscan<<<1, 128>>>(nscanb);
    k_offsets<<<nscanb, SCHUNK>>>(n);
    k_fill<<<(e + 255) / 256, 256>>>(src, dst, e);
    k_convW_all<<<(WTOT + 255) / 256, 256>>>(W0, W1, W2, W3, Wm1, Wm2);

    const int gblocks = (n + 127) / 128;     // 782

    // ---- layer 0: messages M8a = quant(dinv * (x @ W0)) ----
    k_gemm128<<<gblocks, 256, SM128>>>(x, 0, 0, Wf + 0 * WSLOT, 0, 0, M8a, Sca, n);

    // ---- layers 1-3: fused gather+GEMM, ping-pong messages ----
    k_gg<<<gblocks, 256, SM128>>>((const unsigned int*)M8a, Sca, b0, Wf + 1 * WSLOT,
                                  0, M8b, Scb, 0, n);
    k_gg<<<gblocks, 256, SM128>>>((const unsigned int*)M8b, Scb, b1, Wf + 2 * WSLOT,
                                  0, M8a, Sca, 0, n);
    k_gg<<<gblocks, 256, SM128>>>((const unsigned int*)M8a, Sca, b2, Wf + 3 * WSLOT,
                                  0, M8b, Scb, 0, n);

    // ---- MLP1 fused: gather + relu(+b3) + @Wm1 + bm1 -> fp16 F16 ----
    k_gg<<<gblocks, 256, SM128>>>((const unsigned int*)M8b, Scb, b3, Wf + 4 * WSLOT,
                                  bm1, 0, 0, F16, n);

    // ---- MLP2: Cb = F16 @ Wm2 + bm2 (fp32 out) ----
    k_gemm64<<<gblocks, 256, SM64>>>(0, F16, 0, Wf + 5 * WSLOT, bm2, Cb, 0, 0, n);

    // ---- log_softmax -> out ----
    k_logsoftmax<<<(n * 32 + 255) / 256, 256>>>(Cb, out, n);
}

// round 11
// speedup vs baseline: 1.3610x; 1.3610x over previous
#include <cuda_runtime.h>
#include <cuda_fp16.h>
#include <cstdint>
#include <stdint.h>
#include <math.h>

// Problem constants (fixed by the dataset)
#define N_NODES 100000
#define N_EDGES 1600000
#define DIM 128
#define ODIM 64
#define WSLOT 16384
#define WTOT (5 * WSLOT + ODIM * DIM)
#define PADB 272   // smem row stride in bytes, multiple of 16, conflict-free
#define SCHUNK 1024

// ---------------- scratch (static device globals; no allocation) -----------
__device__ signed char g_M8[(size_t)N_NODES * DIM];  // int8 messages
__device__ float       g_sc[N_NODES];                // per-row dequant scale
__device__ __half      g_H16[(size_t)N_NODES * DIM]; // fp16 aggregated features
__device__ __half      g_F16[(size_t)N_NODES * DIM]; // fp16 MLP intermediate
__device__ int         g_deg[N_NODES];
__device__ int         g_cur[N_NODES];
__device__ int         g_off[N_NODES + 1];
__device__ int         g_csr[N_EDGES];
__device__ int         g_bsum[128];
__device__ float       g_dinv[N_NODES];
__device__ __half      g_Wf[WTOT];                   // fp16 transposed weights [N][K]

// ---------------- mma.sync fp16 helper (baseline PTX) ----------------------
__device__ __forceinline__ void mma_f16(float* c, const unsigned int* a,
                                        const unsigned int* b) {
    asm volatile(
        "mma.sync.aligned.m16n8k16.row.col.f32.f16.f16.f32 "
        "{%0,%1,%2,%3}, {%4,%5,%6,%7}, {%8,%9}, {%0,%1,%2,%3};"
        : "+f"(c[0]), "+f"(c[1]), "+f"(c[2]), "+f"(c[3])
        : "r"(a[0]), "r"(a[1]), "r"(a[2]), "r"(a[3]), "r"(b[0]), "r"(b[1]));
}

// ---------------- setup kernels --------------------------------------------
__global__ void k_zero(int n) {
    int i = blockIdx.x * blockDim.x + threadIdx.x;
    if (i < n) { g_deg[i] = 0; g_cur[i] = 0; }
}
__global__ void k_count(const int* __restrict__ dst, int e) {
    int i = blockIdx.x * blockDim.x + threadIdx.x;
    if (i < e) atomicAdd(&g_deg[dst[i]], 1);
}
__global__ void k_bsum(int n) {            // block sums + dinv (deg final here)
    __shared__ int sh[SCHUNK];
    int i = blockIdx.x * SCHUNK + threadIdx.x;
    int d = (i < n) ? g_deg[i] : 0;
    if (i < n) g_dinv[i] = rsqrtf((float)(d + 1));
    sh[threadIdx.x] = d;
    __syncthreads();
    for (int off = SCHUNK / 2; off > 0; off >>= 1) {
        if (threadIdx.x < off) sh[threadIdx.x] += sh[threadIdx.x + off];
        __syncthreads();
    }
    if (threadIdx.x == 0) g_bsum[blockIdx.x] = sh[0];
}
__global__ void k_bscan(int nb) {
    __shared__ int sh[128];
    int v = (threadIdx.x < nb) ? g_bsum[threadIdx.x] : 0;
    sh[threadIdx.x] = v;
    __syncthreads();
    for (int off = 1; off < 128; off <<= 1) {
        int t = (threadIdx.x >= off) ? sh[threadIdx.x - off] : 0;
        __syncthreads();
        sh[threadIdx.x] += t;
        __syncthreads();
    }
    if (threadIdx.x < nb) g_bsum[threadIdx.x] = sh[threadIdx.x] - v;
}
__global__ void k_offsets(int n) {
    __shared__ int sh[SCHUNK];
    int i = blockIdx.x * SCHUNK + threadIdx.x;
    int v = (i < n) ? g_deg[i] : 0;
    sh[threadIdx.x] = v;
    __syncthreads();
    for (int off = 1; off < SCHUNK; off <<= 1) {
        int t = (threadIdx.x >= off) ? sh[threadIdx.x - off] : 0;
        __syncthreads();
        sh[threadIdx.x] += t;
        __syncthreads();
    }
    int excl = g_bsum[blockIdx.x] + sh[threadIdx.x] - v;
    if (i < n) g_off[i] = excl;
    if (i == n - 1) g_off[n] = excl + v;
}
__global__ void k_fill(const int* __restrict__ src, const int* __restrict__ dst, int e) {
    int i = blockIdx.x * blockDim.x + threadIdx.x;
    if (i < e) {
        int d = dst[i];
        int pos = g_off[d] + atomicAdd(&g_cur[d], 1);
        g_csr[pos] = src[i];
    }
}
__global__ void k_convW_all(const float* __restrict__ W0, const float* __restrict__ W1,
                            const float* __restrict__ W2, const float* __restrict__ W3,
                            const float* __restrict__ Wm1, const float* __restrict__ Wm2) {
    int i = blockIdx.x * blockDim.x + threadIdx.x;
    if (i >= WTOT) return;
    int slot = i >> 14;
    int j = i & 16383;
    const float* W;
    int N;
    switch (slot) {
        case 0:  W = W0;  N = 128; break;
        case 1:  W = W1;  N = 128; break;
        case 2:  W = W2;  N = 128; break;
        case 3:  W = W3;  N = 128; break;
        case 4:  W = Wm1; N = 128; break;
        default: W = Wm2; N = 64;  break;
    }
    const int K = 128;
    int nrow = j / K;
    int k = j % K;
    g_Wf[i] = __float2half_rn(W[k * N + nrow]);
}

// ---------------- fp16 HMMA GEMM body ----------------------------------------
// acc = act(A) @ W; act = relu(a+abias) if abias. fp32 accum.
// Modes: C8 != 0 -> int8 message quant (Csc = M*dinv/127)
//        C16 != 0 -> fp16 out = half(acc + cbias)
//        else     -> fused log_softmax over BN cols -> osm (fp32)
template <int BN>
__device__ __forceinline__ void gemm_body(const float* __restrict__ A32,
                                          const __half* __restrict__ A16,
                                          const float* __restrict__ abias,
                                          const __half* __restrict__ Wf,
                                          const float* __restrict__ cbias,
                                          signed char* __restrict__ C8,
                                          float* __restrict__ Csc,
                                          __half* __restrict__ C16,
                                          float* __restrict__ osm,
                                          int n, char* smem)
{
    constexpr int NT = BN / 16;
    const unsigned int A_OF = 0;
    const unsigned int B_OF = 128 * PADB;

    const int tid  = threadIdx.x;
    const int wid  = tid >> 5;
    const int lane = tid & 31;
    const int wr   = wid >> 1;
    const int wc   = wid & 1;
    const int row0 = blockIdx.x * 128;

    // ---- A tile -> fp16 smem, fused relu(+abias)
    for (int i = tid; i < 128 * 16; i += 256) {
        int row = i >> 4;
        int unit = i & 15;
        int grow = row0 + row;
        uint4 u = make_uint4(0, 0, 0, 0);
        __half2* hp = (__half2*)&u;
        if (grow < n) {
            if (A16) {
                u = *(const uint4*)(A16 + (size_t)grow * 128 + unit * 8);
            } else {
                const float4* p = (const float4*)(A32 + (size_t)grow * 128 + unit * 8);
                float4 a0 = p[0], a1 = p[1];
                hp[0] = __floats2half2_rn(a0.x, a0.y);
                hp[1] = __floats2half2_rn(a0.z, a0.w);
                hp[2] = __floats2half2_rn(a1.x, a1.y);
                hp[3] = __floats2half2_rn(a1.z, a1.w);
            }
        }
        if (abias) {
            const float4* b = (const float4*)(abias + unit * 8);
            float4 b0 = b[0], b1 = b[1];
            float bb[8];
            bb[0] = b0.x; bb[1] = b0.y; bb[2] = b0.z; bb[3] = b0.w;
            bb[4] = b1.x; bb[5] = b1.y; bb[6] = b1.z; bb[7] = b1.w;
#pragma unroll
            for (int j = 0; j < 4; j++) {
                float2 f = __half22float2(hp[j]);
                f.x = fmaxf(f.x + bb[2 * j], 0.f);
                f.y = fmaxf(f.y + bb[2 * j + 1], 0.f);
                hp[j] = __floats2half2_rn(f.x, f.y);
            }
        }
        *(uint4*)(smem + A_OF + (unsigned int)row * PADB + (unsigned int)unit * 16) = u;
    }

    // ---- W tile
    for (int i = tid; i < BN * 16; i += 256) {
        int row = i >> 4;
        int unit = i & 15;
        *(uint4*)(smem + B_OF + (unsigned int)row * PADB + (unsigned int)unit * 16) =
            ((const uint4*)Wf)[row * 16 + unit];
    }
    __syncthreads();

    const int g  = lane >> 2;
    const int tg = lane & 3;
    float acc[2][NT][4];
#pragma unroll
    for (int mt = 0; mt < 2; mt++)
#pragma unroll
        for (int nt = 0; nt < NT; nt++)
#pragma unroll
            for (int j = 0; j < 4; j++) acc[mt][nt][j] = 0.f;

#pragma unroll
    for (int ks = 0; ks < 8; ks++) {
        const unsigned int kb = (unsigned int)(ks * 16 + tg * 2) * 2;
        unsigned int a[2][4];
#pragma unroll
        for (int mt = 0; mt < 2; mt++) {
            unsigned int ro = A_OF + (unsigned int)(wr * 32 + mt * 16 + g) * PADB + kb;
            a[mt][0] = *(const unsigned int*)(smem + ro);
            a[mt][1] = *(const unsigned int*)(smem + ro + 8 * PADB);
            a[mt][2] = *(const unsigned int*)(smem + ro + 16);
            a[mt][3] = *(const unsigned int*)(smem + ro + 8 * PADB + 16);
        }
#pragma unroll
        for (int nt = 0; nt < NT; nt++) {
            unsigned int no = B_OF + (unsigned int)(wc * NT * 8 + nt * 8 + g) * PADB + kb;
            unsigned int b[2];
            b[0] = *(const unsigned int*)(smem + no);
            b[1] = *(const unsigned int*)(smem + no + 16);
#pragma unroll
            for (int mt = 0; mt < 2; mt++)
                mma_f16(acc[mt][nt], a[mt], b);
        }
    }

    if (C8) {
        // ---- int8 message quant epilogue
        __syncthreads();
        float* rmax = (float*)smem;
        if (tid < 128) rmax[tid] = 0.f;
        __syncthreads();
#pragma unroll
        for (int mt = 0; mt < 2; mt++) {
            int lr = wr * 32 + mt * 16 + g;
            float m0 = 0.f, m1 = 0.f;
#pragma unroll
            for (int nt = 0; nt < NT; nt++) {
                m0 = fmaxf(m0, fmaxf(fabsf(acc[mt][nt][0]), fabsf(acc[mt][nt][1])));
                m1 = fmaxf(m1, fmaxf(fabsf(acc[mt][nt][2]), fabsf(acc[mt][nt][3])));
            }
            atomicMax((int*)&rmax[lr], __float_as_int(m0));
            atomicMax((int*)&rmax[lr + 8], __float_as_int(m1));
        }
        __syncthreads();
#pragma unroll
        for (int mt = 0; mt < 2; mt++) {
            int lr = wr * 32 + mt * 16 + g;
            int grow = row0 + lr;
            float M0 = rmax[lr], M1 = rmax[lr + 8];
            float q0 = (M0 > 0.f) ? 127.f / M0 : 0.f;
            float q1 = (M1 > 0.f) ? 127.f / M1 : 0.f;
            if (wc == 0 && tg == 0) {
                if (grow < n)     Csc[grow]     = M0 * g_dinv[grow] * (1.f / 127.f);
                if (grow + 8 < n) Csc[grow + 8] = M1 * g_dinv[grow + 8] * (1.f / 127.f);
            }
#pragma unroll
            for (int nt = 0; nt < NT; nt++) {
                int col = wc * NT * 8 + nt * 8 + tg * 2;
                if (grow < n) {
                    int b0 = __float2int_rn(acc[mt][nt][0] * q0);
                    int b1 = __float2int_rn(acc[mt][nt][1] * q0);
                    *(unsigned short*)(C8 + (size_t)grow * 128 + col) =
                        (unsigned short)(((b1 & 0xff) << 8) | (b0 & 0xff));
                }
                if (grow + 8 < n) {
                    int b2 = __float2int_rn(acc[mt][nt][2] * q1);
                    int b3 = __float2int_rn(acc[mt][nt][3] * q1);
                    *(unsigned short*)(C8 + (size_t)(grow + 8) * 128 + col) =
                        (unsigned short)(((b3 & 0xff) << 8) | (b2 & 0xff));
                }
            }
        }
    } else if (C16) {
        // ---- fp16 out (+cbias)
#pragma unroll
        for (int mt = 0; mt < 2; mt++) {
            int r0i = row0 + wr * 32 + mt * 16 + g;
#pragma unroll
            for (int nt = 0; nt < NT; nt++) {
                int col = wc * NT * 8 + nt * 8 + tg * 2;
                float b0 = cbias[col], b1 = cbias[col + 1];
                if (r0i < n)
                    *(__half2*)(C16 + (size_t)r0i * BN + col) =
                        __floats2half2_rn(acc[mt][nt][0] + b0, acc[mt][nt][1] + b1);
                if (r0i + 8 < n)
                    *(__half2*)(C16 + (size_t)(r0i + 8) * BN + col) =
                        __floats2half2_rn(acc[mt][nt][2] + b0, acc[mt][nt][3] + b1);
            }
        }
    } else {
        // ---- fused log_softmax epilogue (BN == 64): full row in this block
        __syncthreads();
        float* sx = (float*)smem;   // 128 rows x stride 68 floats (= PADB bytes)
#pragma unroll
        for (int mt = 0; mt < 2; mt++) {
            int lr = wr * 32 + mt * 16 + g;
#pragma unroll
            for (int nt = 0; nt < NT; nt++) {
                int col = wc * NT * 8 + nt * 8 + tg * 2;
                float b0 = cbias[col], b1 = cbias[col + 1];
                *(float2*)(sx + lr * 68 + col) =
                    make_float2(acc[mt][nt][0] + b0, acc[mt][nt][1] + b1);
                *(float2*)(sx + (lr + 8) * 68 + col) =
                    make_float2(acc[mt][nt][2] + b0, acc[mt][nt][3] + b1);
            }
        }
        __syncthreads();
        for (int r = wid * 16; r < wid * 16 + 16; r++) {
            int grow = row0 + r;
            if (grow >= n) break;
            float v0 = sx[r * 68 + lane];
            float v1 = sx[r * 68 + lane + 32];
            float m = fmaxf(v0, v1);
#pragma unroll
            for (int o = 16; o > 0; o >>= 1)
                m = fmaxf(m, __shfl_xor_sync(0xFFFFFFFFu, m, o));
            float s = expf(v0 - m) + expf(v1 - m);
#pragma unroll
            for (int o = 16; o > 0; o >>= 1)
                s += __shfl_xor_sync(0xFFFFFFFFu, s, o);
            float lg = m + logf(s);
            osm[(size_t)grow * 64 + lane]      = v0 - lg;
            osm[(size_t)grow * 64 + lane + 32] = v1 - lg;
        }
    }
}

__global__ void __launch_bounds__(256, 2)
k_gemm128(const float* A32, const __half* A16, const float* abias,
          const __half* Wf, const float* cbias,
          signed char* C8, float* Csc, __half* C16, int n)
{
    extern __shared__ __align__(16) char smem_dyn[];
    gemm_body<128>(A32, A16, abias, Wf, cbias, C8, Csc, C16, 0, n, smem_dyn);
}

__global__ void __launch_bounds__(256, 2)
k_gemm64s(const __half* A16, const __half* Wf, const float* cbias,
          float* osm, int n)
{
    extern __shared__ __align__(16) char smem_dyn[];
    gemm_body<64>(0, A16, 0, Wf, cbias, 0, 0, 0, osm, n, smem_dyn);
}

// ---------------- CSR pull-gather v3 (int8, 4 rows per warp-load) ----------
// H16[d] = half( dinv[d] * sum_{s in N(d) U {d}} sc[s] * M8[s] )
// Row = 128 int8 = 8 uint4; 8 lanes per row, quarter q = lane>>3 takes
// neighbor j+q. Two loads in flight per step = 8 rows / 1KB outstanding.
#define ACCB(w, f, o)                                              \
    do {                                                           \
        acc[(o) + 0] = fmaf((f), (float)(signed char)((w)), acc[(o) + 0]);        \
        acc[(o) + 1] = fmaf((f), (float)(signed char)((w) >> 8), acc[(o) + 1]);   \
        acc[(o) + 2] = fmaf((f), (float)(signed char)((w) >> 16), acc[(o) + 2]);  \
        acc[(o) + 3] = fmaf((f), (float)(signed char)((w) >> 24), acc[(o) + 3]);  \
    } while (0)
#define ACCU(u, f)                \
    do {                          \
        ACCB((u).x, (f), 0);      \
        ACCB((u).y, (f), 4);      \
        ACCB((u).z, (f), 8);      \
        ACCB((u).w, (f), 12);     \
    } while (0)

__launch_bounds__(256)
__global__ void k_gather(const uint4* __restrict__ M8,   // row = 8 x uint4
                         const float* __restrict__ sc,
                         uint4* __restrict__ H16, int n)  // row = 16 x uint4
{
    int warp = (blockIdx.x * blockDim.x + threadIdx.x) >> 5;
    int lane = threadIdx.x & 31;
    if (warp >= n) return;
    int quarter = lane >> 3;
    int sub = lane & 7;
    int beg = g_off[warp];
    int total = g_off[warp + 1] - beg + 1;   // +1 self loop (virtual idx 0)

    float acc[16];
#pragma unroll
    for (int k = 0; k < 16; k++) acc[k] = 0.f;

    for (int base = 0; base < total; base += 32) {
        int cnt = total - base;
        if (cnt > 32) cnt = 32;
        int vj = base + lane;
        int idx = 0;
        float scv = 0.f;
        if (lane < cnt) {
            idx = (vj == 0) ? warp : g_csr[beg + vj - 1];
            scv = sc[idx];
        }
        for (int j = 0; j < cnt; j += 8) {
            int j0 = j + quarter;
            int j1 = j + 4 + quarter;
            int c0 = (j0 < cnt) ? j0 : 0;
            int c1 = (j1 < cnt) ? j1 : 0;
            int s0 = __shfl_sync(0xFFFFFFFFu, idx, c0);
            int s1 = __shfl_sync(0xFFFFFFFFu, idx, c1);
            float f0 = __shfl_sync(0xFFFFFFFFu, scv, c0);
            float f1 = __shfl_sync(0xFFFFFFFFu, scv, c1);
            if (j0 >= cnt) f0 = 0.f;
            if (j1 >= cnt) f1 = 0.f;
            uint4 u0 = M8[(size_t)s0 * 8 + sub];
            uint4 u1 = M8[(size_t)s1 * 8 + sub];
            ACCU(u0, f0);
            ACCU(u1, f1);
        }
    }

    // combine quarters -> lanes 0-7
#pragma unroll
    for (int k = 0; k < 16; k++) {
        acc[k] += __shfl_down_sync(0xFFFFFFFFu, acc[k], 16);
        acc[k] += __shfl_down_sync(0xFFFFFFFFu, acc[k], 8);
    }

    if (quarter == 0) {
        float di = g_dinv[warp];
        uint4 o0, o1;
        __half2* h0 = (__half2*)&o0;
        __half2* h1 = (__half2*)&o1;
#pragma unroll
        for (int i = 0; i < 4; i++) {
            h0[i] = __floats2half2_rn(acc[2 * i] * di, acc[2 * i + 1] * di);
            h1[i] = __floats2half2_rn(acc[8 + 2 * i] * di, acc[9 + 2 * i] * di);
        }
        H16[(size_t)warp * 16 + sub * 2]     = o0;
        H16[(size_t)warp * 16 + sub * 2 + 1] = o1;
    }
}

// ---------------- host launcher ---------------------------------------------
extern "C" void kernel_launch(void* const* d_in, const int* in_sizes, int n_in,
                              void* d_out, int out_size)
{
    const float* x   = (const float*)d_in[0];
    const int*   ei  = (const int*)d_in[1];
    const float* W0  = (const float*)d_in[2];
    const float* b0  = (const float*)d_in[3];
    const float* W1  = (const float*)d_in[4];
    const float* b1  = (const float*)d_in[5];
    const float* W2  = (const float*)d_in[6];
    const float* b2  = (const float*)d_in[7];
    const float* W3  = (const float*)d_in[8];
    const float* b3  = (const float*)d_in[9];
    const float* Wm1 = (const float*)d_in[10];
    const float* bm1 = (const float*)d_in[11];
    const float* Wm2 = (const float*)d_in[12];
    const float* bm2 = (const float*)d_in[13];
    float* out = (float*)d_out;

    const int n = in_sizes[0] / DIM;      // 100000
    const int e = in_sizes[1] / 2;        // 1600000
    const int* src = ei;
    const int* dst = ei + e;

    signed char* M8 = 0;
    float* Sc = 0;
    __half* H16 = 0;
    __half* F16 = 0;
    __half* Wf = 0;
    cudaGetSymbolAddress((void**)&M8,  g_M8);
    cudaGetSymbolAddress((void**)&Sc,  g_sc);
    cudaGetSymbolAddress((void**)&H16, g_H16);
    cudaGetSymbolAddress((void**)&F16, g_F16);
    cudaGetSymbolAddress((void**)&Wf,  g_Wf);

    const int SM128 = 128 * PADB + 128 * PADB;   // 69632
    const int SM64  = 128 * PADB + 64 * PADB;    // 52224
    cudaFuncSetAttribute(k_gemm128, cudaFuncAttributeMaxDynamicSharedMemorySize, SM128);
    cudaFuncSetAttribute(k_gemm64s, cudaFuncAttributeMaxDynamicSharedMemorySize, SM64);

    const int nscanb = (n + SCHUNK - 1) / SCHUNK;

    // ---- setup: degrees, CSR, dinv, weights ----
    k_zero<<<(n + 255) / 256, 256>>>(n);
    k_count<<<(e + 255) / 256, 256>>>(dst, e);
    k_bsum<<<nscanb, SCHUNK>>>(n);
    k_bscan<<<1, 128>>>(nscanb);
    k_offsets<<<nscanb, SCHUNK>>>(n);
    k_fill<<<(e + 255) / 256, 256>>>(src, dst, e);
    k_convW_all<<<(WTOT + 255) / 256, 256>>>(W0, W1, W2, W3, Wm1, Wm2);

    const int gblocks = (n + 127) / 128;                 // 782
    const int gatherb = (n * 32 + 255) / 256;            // 12500

    // ---- 4 GCN layers: M8/Sc = quant(dinv*(act(H)@W)); H16 = gather ----
    k_gemm128<<<gblocks, 256, SM128>>>(x, 0, 0, Wf + 0 * WSLOT, 0, M8, Sc, 0, n);
    k_gather<<<gatherb, 256>>>((const uint4*)M8, Sc, (uint4*)H16, n);

    k_gemm128<<<gblocks, 256, SM128>>>(0, H16, b0, Wf + 1 * WSLOT, 0, M8, Sc, 0, n);
    k_gather<<<gatherb, 256>>>((const uint4*)M8, Sc, (uint4*)H16, n);

    k_gemm128<<<gblocks, 256, SM128>>>(0, H16, b1, Wf + 2 * WSLOT, 0, M8, Sc, 0, n);
    k_gather<<<gatherb, 256>>>((const uint4*)M8, Sc, (uint4*)H16, n);

    k_gemm128<<<gblocks, 256, SM128>>>(0, H16, b2, Wf + 3 * WSLOT, 0, M8, Sc, 0, n);
    k_gather<<<gatherb, 256>>>((const uint4*)M8, Sc, (uint4*)H16, n);

    // ---- MLP1: F16 = half(relu(H16 + b3) @ Wm1 + bm1) ----
    k_gemm128<<<gblocks, 256, SM128>>>(0, H16, b3, Wf + 4 * WSLOT, bm1, 0, 0, F16, n);

    // ---- MLP2 + fused log_softmax -> out ----
    k_gemm64s<<<gblocks, 256, SM64>>>(F16, Wf + 5 * WSLOT, bm2, out, n);
}

// round 12
// speedup vs baseline: 1.4706x; 1.0806x over previous
#include <cuda_runtime.h>
#include <cuda_fp16.h>
#include <cstdint>
#include <stdint.h>
#include <math.h>

// Problem constants (fixed by the dataset)
#define N_NODES 100000
#define N_EDGES 1600000
#define DIM 128
#define ODIM 64
#define WSLOT 16384
#define WTOT (5 * WSLOT + ODIM * DIM)
#define PADB 272   // smem row stride in bytes, multiple of 16, conflict-free
#define SCHUNK 1024

// ---------------- scratch (static device globals; no allocation) -----------
__device__ signed char g_M8[(size_t)N_NODES * DIM];  // int8 messages
__device__ float       g_sc[N_NODES];                // per-row dequant scale
__device__ __half      g_H16[(size_t)N_NODES * DIM]; // fp16 aggregated features
__device__ __half      g_F16[(size_t)N_NODES * DIM]; // fp16 MLP intermediate
__device__ int         g_deg[N_NODES];
__device__ int         g_cur[N_NODES];
__device__ int         g_off[N_NODES + 1];
__device__ int         g_csr[N_EDGES];
__device__ int         g_bsum[128];
__device__ float       g_dinv[N_NODES];
__device__ __half      g_Wf[WTOT];                   // fp16 transposed weights [N][K]

// ---------------- mma.sync fp16 helper (baseline PTX) ----------------------
__device__ __forceinline__ void mma_f16(float* c, const unsigned int* a,
                                        const unsigned int* b) {
    asm volatile(
        "mma.sync.aligned.m16n8k16.row.col.f32.f16.f16.f32 "
        "{%0,%1,%2,%3}, {%4,%5,%6,%7}, {%8,%9}, {%0,%1,%2,%3};"
        : "+f"(c[0]), "+f"(c[1]), "+f"(c[2]), "+f"(c[3])
        : "r"(a[0]), "r"(a[1]), "r"(a[2]), "r"(a[3]), "r"(b[0]), "r"(b[1]));
}

// ---------------- setup kernels --------------------------------------------
__global__ void k_zero(int n) {
    int i = blockIdx.x * blockDim.x + threadIdx.x;
    if (i < n) { g_deg[i] = 0; g_cur[i] = 0; }
}
__global__ void k_count(const int* __restrict__ dst, int e) {
    int i = blockIdx.x * blockDim.x + threadIdx.x;
    if (i < e) atomicAdd(&g_deg[dst[i]], 1);
}
__global__ void k_bsum(int n) {            // block sums + dinv (deg final here)
    __shared__ int sh[SCHUNK];
    int i = blockIdx.x * SCHUNK + threadIdx.x;
    int d = (i < n) ? g_deg[i] : 0;
    if (i < n) g_dinv[i] = rsqrtf((float)(d + 1));
    sh[threadIdx.x] = d;
    __syncthreads();
    for (int off = SCHUNK / 2; off > 0; off >>= 1) {
        if (threadIdx.x < off) sh[threadIdx.x] += sh[threadIdx.x + off];
        __syncthreads();
    }
    if (threadIdx.x == 0) g_bsum[blockIdx.x] = sh[0];
}
__global__ void k_bscan(int nb) {
    __shared__ int sh[128];
    int v = (threadIdx.x < nb) ? g_bsum[threadIdx.x] : 0;
    sh[threadIdx.x] = v;
    __syncthreads();
    for (int off = 1; off < 128; off <<= 1) {
        int t = (threadIdx.x >= off) ? sh[threadIdx.x - off] : 0;
        __syncthreads();
        sh[threadIdx.x] += t;
        __syncthreads();
    }
    if (threadIdx.x < nb) g_bsum[threadIdx.x] = sh[threadIdx.x] - v;
}
__global__ void k_offsets(int n) {
    __shared__ int sh[SCHUNK];
    int i = blockIdx.x * SCHUNK + threadIdx.x;
    int v = (i < n) ? g_deg[i] : 0;
    sh[threadIdx.x] = v;
    __syncthreads();
    for (int off = 1; off < SCHUNK; off <<= 1) {
        int t = (threadIdx.x >= off) ? sh[threadIdx.x - off] : 0;
        __syncthreads();
        sh[threadIdx.x] += t;
        __syncthreads();
    }
    int excl = g_bsum[blockIdx.x] + sh[threadIdx.x] - v;
    if (i < n) g_off[i] = excl;
    if (i == n - 1) g_off[n] = excl + v;
}
__global__ void k_fill(const int* __restrict__ src, const int* __restrict__ dst, int e) {
    int i = blockIdx.x * blockDim.x + threadIdx.x;
    if (i < e) {
        int d = dst[i];
        int pos = g_off[d] + atomicAdd(&g_cur[d], 1);
        g_csr[pos] = src[i];
    }
}
__global__ void k_convW_all(const float* __restrict__ W0, const float* __restrict__ W1,
                            const float* __restrict__ W2, const float* __restrict__ W3,
                            const float* __restrict__ Wm1, const float* __restrict__ Wm2) {
    int i = blockIdx.x * blockDim.x + threadIdx.x;
    if (i >= WTOT) return;
    int slot = i >> 14;
    int j = i & 16383;
    const float* W;
    int N;
    switch (slot) {
        case 0:  W = W0;  N = 128; break;
        case 1:  W = W1;  N = 128; break;
        case 2:  W = W2;  N = 128; break;
        case 3:  W = W3;  N = 128; break;
        case 4:  W = Wm1; N = 128; break;
        default: W = Wm2; N = 64;  break;
    }
    const int K = 128;
    int nrow = j / K;
    int k = j % K;
    g_Wf[i] = __float2half_rn(W[k * N + nrow]);
}

// ---------------- fp16 HMMA GEMM body ----------------------------------------
// acc = act(A) @ W; act = relu(a+abias) if abias. fp32 accum.
// Modes: C8 != 0 -> int8 message quant (Csc = M*dinv/127)
//        C16 != 0 -> fp16 out = half(acc + cbias)
//        else     -> fused log_softmax over BN cols -> osm (fp32)
template <int BN>
__device__ __forceinline__ void gemm_body(const float* __restrict__ A32,
                                          const __half* __restrict__ A16,
                                          const float* __restrict__ abias,
                                          const __half* __restrict__ Wf,
                                          const float* __restrict__ cbias,
                                          signed char* __restrict__ C8,
                                          float* __restrict__ Csc,
                                          __half* __restrict__ C16,
                                          float* __restrict__ osm,
                                          int n, char* smem)
{
    constexpr int NT = BN / 16;
    const unsigned int A_OF = 0;
    const unsigned int B_OF = 128 * PADB;

    const int tid  = threadIdx.x;
    const int wid  = tid >> 5;
    const int lane = tid & 31;
    const int wr   = wid >> 1;
    const int wc   = wid & 1;
    const int row0 = blockIdx.x * 128;

    // ---- A tile -> fp16 smem, fused relu(+abias)
    for (int i = tid; i < 128 * 16; i += 256) {
        int row = i >> 4;
        int unit = i & 15;
        int grow = row0 + row;
        uint4 u = make_uint4(0, 0, 0, 0);
        __half2* hp = (__half2*)&u;
        if (grow < n) {
            if (A16) {
                u = *(const uint4*)(A16 + (size_t)grow * 128 + unit * 8);
            } else {
                const float4* p = (const float4*)(A32 + (size_t)grow * 128 + unit * 8);
                float4 a0 = p[0], a1 = p[1];
                hp[0] = __floats2half2_rn(a0.x, a0.y);
                hp[1] = __floats2half2_rn(a0.z, a0.w);
                hp[2] = __floats2half2_rn(a1.x, a1.y);
                hp[3] = __floats2half2_rn(a1.z, a1.w);
            }
        }
        if (abias) {
            const float4* b = (const float4*)(abias + unit * 8);
            float4 b0 = b[0], b1 = b[1];
            float bb[8];
            bb[0] = b0.x; bb[1] = b0.y; bb[2] = b0.z; bb[3] = b0.w;
            bb[4] = b1.x; bb[5] = b1.y; bb[6] = b1.z; bb[7] = b1.w;
#pragma unroll
            for (int j = 0; j < 4; j++) {
                float2 f = __half22float2(hp[j]);
                f.x = fmaxf(f.x + bb[2 * j], 0.f);
                f.y = fmaxf(f.y + bb[2 * j + 1], 0.f);
                hp[j] = __floats2half2_rn(f.x, f.y);
            }
        }
        *(uint4*)(smem + A_OF + (unsigned int)row * PADB + (unsigned int)unit * 16) = u;
    }

    // ---- W tile
    for (int i = tid; i < BN * 16; i += 256) {
        int row = i >> 4;
        int unit = i & 15;
        *(uint4*)(smem + B_OF + (unsigned int)row * PADB + (unsigned int)unit * 16) =
            ((const uint4*)Wf)[row * 16 + unit];
    }
    __syncthreads();

    const int g  = lane >> 2;
    const int tg = lane & 3;
    float acc[2][NT][4];
#pragma unroll
    for (int mt = 0; mt < 2; mt++)
#pragma unroll
        for (int nt = 0; nt < NT; nt++)
#pragma unroll
            for (int j = 0; j < 4; j++) acc[mt][nt][j] = 0.f;

#pragma unroll
    for (int ks = 0; ks < 8; ks++) {
        const unsigned int kb = (unsigned int)(ks * 16 + tg * 2) * 2;
        unsigned int a[2][4];
#pragma unroll
        for (int mt = 0; mt < 2; mt++) {
            unsigned int ro = A_OF + (unsigned int)(wr * 32 + mt * 16 + g) * PADB + kb;
            a[mt][0] = *(const unsigned int*)(smem + ro);
            a[mt][1] = *(const unsigned int*)(smem + ro + 8 * PADB);
            a[mt][2] = *(const unsigned int*)(smem + ro + 16);
            a[mt][3] = *(const unsigned int*)(smem + ro + 8 * PADB + 16);
        }
#pragma unroll
        for (int nt = 0; nt < NT; nt++) {
            unsigned int no = B_OF + (unsigned int)(wc * NT * 8 + nt * 8 + g) * PADB + kb;
            unsigned int b[2];
            b[0] = *(const unsigned int*)(smem + no);
            b[1] = *(const unsigned int*)(smem + no + 16);
#pragma unroll
            for (int mt = 0; mt < 2; mt++)
                mma_f16(acc[mt][nt], a[mt], b);
        }
    }

    if (C8) {
        // ---- int8 message quant epilogue
        __syncthreads();
        float* rmax = (float*)smem;
        if (tid < 128) rmax[tid] = 0.f;
        __syncthreads();
#pragma unroll
        for (int mt = 0; mt < 2; mt++) {
            int lr = wr * 32 + mt * 16 + g;
            float m0 = 0.f, m1 = 0.f;
#pragma unroll
            for (int nt = 0; nt < NT; nt++) {
                m0 = fmaxf(m0, fmaxf(fabsf(acc[mt][nt][0]), fabsf(acc[mt][nt][1])));
                m1 = fmaxf(m1, fmaxf(fabsf(acc[mt][nt][2]), fabsf(acc[mt][nt][3])));
            }
            atomicMax((int*)&rmax[lr], __float_as_int(m0));
            atomicMax((int*)&rmax[lr + 8], __float_as_int(m1));
        }
        __syncthreads();
#pragma unroll
        for (int mt = 0; mt < 2; mt++) {
            int lr = wr * 32 + mt * 16 + g;
            int grow = row0 + lr;
            float M0 = rmax[lr], M1 = rmax[lr + 8];
            float q0 = (M0 > 0.f) ? 127.f / M0 : 0.f;
            float q1 = (M1 > 0.f) ? 127.f / M1 : 0.f;
            if (wc == 0 && tg == 0) {
                if (grow < n)     Csc[grow]     = M0 * g_dinv[grow] * (1.f / 127.f);
                if (grow + 8 < n) Csc[grow + 8] = M1 * g_dinv[grow + 8] * (1.f / 127.f);
            }
#pragma unroll
            for (int nt = 0; nt < NT; nt++) {
                int col = wc * NT * 8 + nt * 8 + tg * 2;
                if (grow < n) {
                    int b0 = __float2int_rn(acc[mt][nt][0] * q0);
                    int b1 = __float2int_rn(acc[mt][nt][1] * q0);
                    *(unsigned short*)(C8 + (size_t)grow * 128 + col) =
                        (unsigned short)(((b1 & 0xff) << 8) | (b0 & 0xff));
                }
                if (grow + 8 < n) {
                    int b2 = __float2int_rn(acc[mt][nt][2] * q1);
                    int b3 = __float2int_rn(acc[mt][nt][3] * q1);
                    *(unsigned short*)(C8 + (size_t)(grow + 8) * 128 + col) =
                        (unsigned short)(((b3 & 0xff) << 8) | (b2 & 0xff));
                }
            }
        }
    } else if (C16) {
        // ---- fp16 out (+cbias)
#pragma unroll
        for (int mt = 0; mt < 2; mt++) {
            int r0i = row0 + wr * 32 + mt * 16 + g;
#pragma unroll
            for (int nt = 0; nt < NT; nt++) {
                int col = wc * NT * 8 + nt * 8 + tg * 2;
                float b0 = cbias[col], b1 = cbias[col + 1];
                if (r0i < n)
                    *(__half2*)(C16 + (size_t)r0i * BN + col) =
                        __floats2half2_rn(acc[mt][nt][0] + b0, acc[mt][nt][1] + b1);
                if (r0i + 8 < n)
                    *(__half2*)(C16 + (size_t)(r0i + 8) * BN + col) =
                        __floats2half2_rn(acc[mt][nt][2] + b0, acc[mt][nt][3] + b1);
            }
        }
    } else {
        // ---- fused log_softmax epilogue (BN == 64): full row in this block
        __syncthreads();
        float* sx = (float*)smem;   // 128 rows x stride 68 floats (= PADB bytes)
#pragma unroll
        for (int mt = 0; mt < 2; mt++) {
            int lr = wr * 32 + mt * 16 + g;
#pragma unroll
            for (int nt = 0; nt < NT; nt++) {
                int col = wc * NT * 8 + nt * 8 + tg * 2;
                float b0 = cbias[col], b1 = cbias[col + 1];
                *(float2*)(sx + lr * 68 + col) =
                    make_float2(acc[mt][nt][0] + b0, acc[mt][nt][1] + b1);
                *(float2*)(sx + (lr + 8) * 68 + col) =
                    make_float2(acc[mt][nt][2] + b0, acc[mt][nt][3] + b1);
            }
        }
        __syncthreads();
        for (int r = wid * 16; r < wid * 16 + 16; r++) {
            int grow = row0 + r;
            if (grow >= n) break;
            float v0 = sx[r * 68 + lane];
            float v1 = sx[r * 68 + lane + 32];
            float m = fmaxf(v0, v1);
#pragma unroll
            for (int o = 16; o > 0; o >>= 1)
                m = fmaxf(m, __shfl_xor_sync(0xFFFFFFFFu, m, o));
            float s = expf(v0 - m) + expf(v1 - m);
#pragma unroll
            for (int o = 16; o > 0; o >>= 1)
                s += __shfl_xor_sync(0xFFFFFFFFu, s, o);
            float lg = m + logf(s);
            osm[(size_t)grow * 64 + lane]      = v0 - lg;
            osm[(size_t)grow * 64 + lane + 32] = v1 - lg;
        }
    }
}

__global__ void __launch_bounds__(256, 2)
k_gemm128(const float* A32, const __half* A16, const float* abias,
          const __half* Wf, const float* cbias,
          signed char* C8, float* Csc, __half* C16, int n)
{
    extern __shared__ __align__(16) char smem_dyn[];
    gemm_body<128>(A32, A16, abias, Wf, cbias, C8, Csc, C16, 0, n, smem_dyn);
}

__global__ void __launch_bounds__(256, 2)
k_gemm64s(const __half* A16, const __half* Wf, const float* cbias,
          float* osm, int n)
{
    extern __shared__ __align__(16) char smem_dyn[];
    gemm_body<64>(0, A16, 0, Wf, cbias, 0, 0, 0, osm, n, smem_dyn);
}

// ---------------- CSR pull-gather (R9 layout: uint2, 2 rows/load) ----------
// H16[d] = half( dinv[d] * sum_{s in N(d) U {d}} sc[s] * M8[s] )
// Row = 128 int8 = 16 uint2; lanes 0-15 neighbor j, lanes 16-31 neighbor j+1.
// Unrolled to 4 loads (8 rows) in flight per step.
__device__ __forceinline__ void addq(float* a, uint2 u, float sc) {
    a[0] = fmaf(sc, (float)(signed char)(u.x), a[0]);
    a[1] = fmaf(sc, (float)(signed char)(u.x >> 8), a[1]);
    a[2] = fmaf(sc, (float)(signed char)(u.x >> 16), a[2]);
    a[3] = fmaf(sc, (float)(signed char)(u.x >> 24), a[3]);
    a[4] = fmaf(sc, (float)(signed char)(u.y), a[4]);
    a[5] = fmaf(sc, (float)(signed char)(u.y >> 8), a[5]);
    a[6] = fmaf(sc, (float)(signed char)(u.y >> 16), a[6]);
    a[7] = fmaf(sc, (float)(signed char)(u.y >> 24), a[7]);
}

__launch_bounds__(256)
__global__ void k_gather(const uint2* __restrict__ M8,   // row = 16 uint2
                         const float* __restrict__ sc,
                         uint4* __restrict__ H16, int n)  // row = 16 uint4
{
    int warp = (blockIdx.x * blockDim.x + threadIdx.x) >> 5;
    int lane = threadIdx.x & 31;
    if (warp >= n) return;
    int half = lane >> 4;
    int sub  = lane & 15;
    int beg = g_off[warp];
    int total = g_off[warp + 1] - beg + 1;   // +1 self loop (virtual idx 0)

    float acc[8];
#pragma unroll
    for (int k = 0; k < 8; k++) acc[k] = 0.f;

    for (int base = 0; base < total; base += 32) {
        int cnt = total - base;
        if (cnt > 32) cnt = 32;
        int vj = base + lane;
        int idx = 0;
        if (lane < cnt) idx = (vj == 0) ? warp : g_csr[beg + vj - 1];
        int j = 0;
        for (; j + 8 <= cnt; j += 8) {
            int s0 = __shfl_sync(0xFFFFFFFFu, idx, j + half);
            int s1 = __shfl_sync(0xFFFFFFFFu, idx, j + 2 + half);
            int s2 = __shfl_sync(0xFFFFFFFFu, idx, j + 4 + half);
            int s3 = __shfl_sync(0xFFFFFFFFu, idx, j + 6 + half);
            uint2 u0 = M8[(size_t)s0 * 16 + sub];
            float f0 = sc[s0];
            uint2 u1 = M8[(size_t)s1 * 16 + sub];
            float f1 = sc[s1];
            uint2 u2 = M8[(size_t)s2 * 16 + sub];
            float f2 = sc[s2];
            uint2 u3 = M8[(size_t)s3 * 16 + sub];
            float f3 = sc[s3];
            addq(acc, u0, f0);
            addq(acc, u1, f1);
            addq(acc, u2, f2);
            addq(acc, u3, f3);
        }
        if (j + 4 <= cnt) {
            int s0 = __shfl_sync(0xFFFFFFFFu, idx, j + half);
            int s1 = __shfl_sync(0xFFFFFFFFu, idx, j + 2 + half);
            uint2 u0 = M8[(size_t)s0 * 16 + sub];
            float f0 = sc[s0];
            uint2 u1 = M8[(size_t)s1 * 16 + sub];
            float f1 = sc[s1];
            addq(acc, u0, f0);
            addq(acc, u1, f1);
            j += 4;
        }
        if (j + 2 <= cnt) {
            int s = __shfl_sync(0xFFFFFFFFu, idx, j + half);
            uint2 u = M8[(size_t)s * 16 + sub];
            addq(acc, u, sc[s]);
            j += 2;
        }
        if (j < cnt) {
            int s = __shfl_sync(0xFFFFFFFFu, idx, j);
            if (half == 0) {
                uint2 u = M8[(size_t)s * 16 + sub];
                addq(acc, u, sc[s]);
            }
        }
    }

    // combine the two halves: lanes 0-15 accumulate lane+16's partial
#pragma unroll
    for (int k = 0; k < 8; k++)
        acc[k] += __shfl_down_sync(0xFFFFFFFFu, acc[k], 16);

    if (half == 0) {
        float di = g_dinv[warp];
        uint4 o;
        __half2* oh = (__half2*)&o;
#pragma unroll
        for (int i = 0; i < 4; i++)
            oh[i] = __floats2half2_rn(acc[2 * i] * di, acc[2 * i + 1] * di);
        H16[(size_t)warp * 16 + sub] = o;
    }
}

// ---------------- host launcher ---------------------------------------------
extern "C" void kernel_launch(void* const* d_in, const int* in_sizes, int n_in,
                              void* d_out, int out_size)
{
    const float* x   = (const float*)d_in[0];
    const int*   ei  = (const int*)d_in[1];
    const float* W0  = (const float*)d_in[2];
    const float* b0  = (const float*)d_in[3];
    const float* W1  = (const float*)d_in[4];
    const float* b1  = (const float*)d_in[5];
    const float* W2  = (const float*)d_in[6];
    const float* b2  = (const float*)d_in[7];
    const float* W3  = (const float*)d_in[8];
    const float* b3  = (const float*)d_in[9];
    const float* Wm1 = (const float*)d_in[10];
    const float* bm1 = (const float*)d_in[11];
    const float* Wm2 = (const float*)d_in[12];
    const float* bm2 = (const float*)d_in[13];
    float* out = (float*)d_out;

    const int n = in_sizes[0] / DIM;      // 100000
    const int e = in_sizes[1] / 2;        // 1600000
    const int* src = ei;
    const int* dst = ei + e;

    signed char* M8 = 0;
    float* Sc = 0;
    __half* H16 = 0;
    __half* F16 = 0;
    __half* Wf = 0;
    cudaGetSymbolAddress((void**)&M8,  g_M8);
    cudaGetSymbolAddress((void**)&Sc,  g_sc);
    cudaGetSymbolAddress((void**)&H16, g_H16);
    cudaGetSymbolAddress((void**)&F16, g_F16);
    cudaGetSymbolAddress((void**)&Wf,  g_Wf);

    const int SM128 = 128 * PADB + 128 * PADB;   // 69632
    const int SM64  = 128 * PADB + 64 * PADB;    // 52224
    cudaFuncSetAttribute(k_gemm128, cudaFuncAttributeMaxDynamicSharedMemorySize, SM128);
    cudaFuncSetAttribute(k_gemm64s, cudaFuncAttributeMaxDynamicSharedMemorySize, SM64);

    const int nscanb = (n + SCHUNK - 1) / SCHUNK;

    // ---- setup: degrees, CSR, dinv, weights ----
    k_zero<<<(n + 255) / 256, 256>>>(n);
    k_count<<<(e + 255) / 256, 256>>>(dst, e);
    k_bsum<<<nscanb, SCHUNK>>>(n);
    k_bscan<<<1, 128>>>(nscanb);
    k_offsets<<<nscanb, SCHUNK>>>(n);
    k_fill<<<(e + 255) / 256, 256>>>(src, dst, e);
    k_convW_all<<<(WTOT + 255) / 256, 256>>>(W0, W1, W2, W3, Wm1, Wm2);

    const int gblocks = (n + 127) / 128;                 // 782
    const int gatherb = (n * 32 + 255) / 256;            // 12500

    // ---- 4 GCN layers: M8/Sc = quant(dinv*(act(H)@W)); H16 = gather ----
    k_gemm128<<<gblocks, 256, SM128>>>(x, 0, 0, Wf + 0 * WSLOT, 0, M8, Sc, 0, n);
    k_gather<<<gatherb, 256>>>((const uint2*)M8, Sc, (uint4*)H16, n);

    k_gemm128<<<gblocks, 256, SM128>>>(0, H16, b0, Wf + 1 * WSLOT, 0, M8, Sc, 0, n);
    k_gather<<<gatherb, 256>>>((const uint2*)M8, Sc, (uint4*)H16, n);

    k_gemm128<<<gblocks, 256, SM128>>>(0, H16, b1, Wf + 2 * WSLOT, 0, M8, Sc, 0, n);
    k_gather<<<gatherb, 256>>>((const uint2*)M8, Sc, (uint4*)H16, n);

    k_gemm128<<<gblocks, 256, SM128>>>(0, H16, b2, Wf + 3 * WSLOT, 0, M8, Sc, 0, n);
    k_gather<<<gatherb, 256>>>((const uint2*)M8, Sc, (uint4*)H16, n);

    // ---- MLP1: F16 = half(relu(H16 + b3) @ Wm1 + bm1) ----
    k_gemm128<<<gblocks, 256, SM128>>>(0, H16, b3, Wf + 4 * WSLOT, bm1, 0, 0, F16, n);

    // ---- MLP2 + fused log_softmax -> out ----
    k_gemm64s<<<gblocks, 256, SM64>>>(F16, Wf + 5 * WSLOT, bm2, out, n);
}

// round 13
// speedup vs baseline: 1.5018x; 1.0212x over previous
#include <cuda_runtime.h>
#include <cuda_fp16.h>
#include <cstdint>
#include <stdint.h>
#include <math.h>

// Problem constants (fixed by the dataset)
#define N_NODES 100000
#define N_EDGES 1600000
#define DIM 128
#define ODIM 64
#define WSLOT 16384
#define WTOT (5 * WSLOT + ODIM * DIM)
#define PADB 272   // smem row stride in bytes, multiple of 16, conflict-free
#define SCHUNK 1024

// ---------------- scratch (static device globals; no allocation) -----------
__device__ signed char g_M8[(size_t)N_NODES * DIM];  // int8 messages
__device__ float       g_sc[N_NODES];                // per-row dequant scale
__device__ __half      g_H16[(size_t)N_NODES * DIM]; // fp16 aggregated features
__device__ __half      g_F16[(size_t)N_NODES * DIM]; // fp16 MLP intermediate
__device__ int         g_deg[N_NODES];
__device__ int         g_cur[N_NODES];
__device__ int         g_off[N_NODES + 1];
__device__ int         g_csr[N_EDGES];
__device__ int         g_bsum[128];
__device__ float       g_dinv[N_NODES];
__device__ __half      g_Wf[WTOT];                   // fp16 transposed weights [N][K]

// ---------------- mma.sync fp16 helper (baseline PTX) ----------------------
__device__ __forceinline__ void mma_f16(float* c, const unsigned int* a,
                                        const unsigned int* b) {
    asm volatile(
        "mma.sync.aligned.m16n8k16.row.col.f32.f16.f16.f32 "
        "{%0,%1,%2,%3}, {%4,%5,%6,%7}, {%8,%9}, {%0,%1,%2,%3};"
        : "+f"(c[0]), "+f"(c[1]), "+f"(c[2]), "+f"(c[3])
        : "r"(a[0]), "r"(a[1]), "r"(a[2]), "r"(a[3]), "r"(b[0]), "r"(b[1]));
}

// ---------------- setup kernels --------------------------------------------
__global__ void k_zero(int n) {
    int i = blockIdx.x * blockDim.x + threadIdx.x;
    if (i < n) g_deg[i] = 0;
}
__global__ void k_count(const int* __restrict__ dst, int e) {
    int i = blockIdx.x * blockDim.x + threadIdx.x;
    if (i < e) atomicAdd(&g_deg[dst[i]], 1);
}
__global__ void k_bsum(int n) {            // block sums + dinv (deg final here)
    __shared__ int sh[SCHUNK];
    int i = blockIdx.x * SCHUNK + threadIdx.x;
    int d = (i < n) ? g_deg[i] : 0;
    if (i < n) g_dinv[i] = rsqrtf((float)(d + 1));
    sh[threadIdx.x] = d;
    __syncthreads();
    for (int off = SCHUNK / 2; off > 0; off >>= 1) {
        if (threadIdx.x < off) sh[threadIdx.x] += sh[threadIdx.x + off];
        __syncthreads();
    }
    if (threadIdx.x == 0) g_bsum[blockIdx.x] = sh[0];
}
__global__ void k_bscan(int nb) {
    __shared__ int sh[128];
    int v = (threadIdx.x < nb) ? g_bsum[threadIdx.x] : 0;
    sh[threadIdx.x] = v;
    __syncthreads();
    for (int off = 1; off < 128; off <<= 1) {
        int t = (threadIdx.x >= off) ? sh[threadIdx.x - off] : 0;
        __syncthreads();
        sh[threadIdx.x] += t;
        __syncthreads();
    }
    if (threadIdx.x < nb) g_bsum[threadIdx.x] = sh[threadIdx.x] - v;
}
__global__ void k_offsets(int n) {
    __shared__ int sh[SCHUNK];
    int i = blockIdx.x * SCHUNK + threadIdx.x;
    int v = (i < n) ? g_deg[i] : 0;
    sh[threadIdx.x] = v;
    __syncthreads();
    for (int off = 1; off < SCHUNK; off <<= 1) {
        int t = (threadIdx.x >= off) ? sh[threadIdx.x - off] : 0;
        __syncthreads();
        sh[threadIdx.x] += t;
        __syncthreads();
    }
    int excl = g_bsum[blockIdx.x] + sh[threadIdx.x] - v;
    if (i < n) { g_off[i] = excl; g_cur[i] = excl; }   // cur preloaded as cursor
    if (i == n - 1) g_off[n] = excl + v;
}
__global__ void k_fill(const int* __restrict__ src, const int* __restrict__ dst, int e) {
    int i = blockIdx.x * blockDim.x + threadIdx.x;
    if (i < e) {
        int pos = atomicAdd(&g_cur[dst[i]], 1);
        g_csr[pos] = src[i];
    }
}
__global__ void k_convW_all(const float* __restrict__ W0, const float* __restrict__ W1,
                            const float* __restrict__ W2, const float* __restrict__ W3,
                            const float* __restrict__ Wm1, const float* __restrict__ Wm2) {
    int i = blockIdx.x * blockDim.x + threadIdx.x;
    if (i >= WTOT) return;
    int slot = i >> 14;
    int j = i & 16383;
    const float* W;
    int N;
    switch (slot) {
        case 0:  W = W0;  N = 128; break;
        case 1:  W = W1;  N = 128; break;
        case 2:  W = W2;  N = 128; break;
        case 3:  W = W3;  N = 128; break;
        case 4:  W = Wm1; N = 128; break;
        default: W = Wm2; N = 64;  break;
    }
    const int K = 128;
    int nrow = j / K;
    int k = j % K;
    g_Wf[i] = __float2half_rn(W[k * N + nrow]);
}

// ---------------- fp16 HMMA GEMM body ----------------------------------------
// acc = act(A) @ W; act = relu(a+abias) if abias. fp32 accum.
// Modes: C8 != 0 -> int8 message quant (Csc = M*dinv/127)
//        C16 != 0 -> fp16 out = half(acc + cbias)
//        else     -> fused log_softmax over BN cols -> osm (fp32)
template <int BN>
__device__ __forceinline__ void gemm_body(const float* __restrict__ A32,
                                          const __half* __restrict__ A16,
                                          const float* __restrict__ abias,
                                          const __half* __restrict__ Wf,
                                          const float* __restrict__ cbias,
                                          signed char* __restrict__ C8,
                                          float* __restrict__ Csc,
                                          __half* __restrict__ C16,
                                          float* __restrict__ osm,
                                          int n, char* smem)
{
    constexpr int NT = BN / 16;
    const unsigned int A_OF = 0;
    const unsigned int B_OF = 128 * PADB;

    const int tid  = threadIdx.x;
    const int wid  = tid >> 5;
    const int lane = tid & 31;
    const int wr   = wid >> 1;
    const int wc   = wid & 1;
    const int row0 = blockIdx.x * 128;

    // ---- A tile -> fp16 smem, fused relu(+abias)
    for (int i = tid; i < 128 * 16; i += 256) {
        int row = i >> 4;
        int unit = i & 15;
        int grow = row0 + row;
        uint4 u = make_uint4(0, 0, 0, 0);
        __half2* hp = (__half2*)&u;
        if (grow < n) {
            if (A16) {
                u = *(const uint4*)(A16 + (size_t)grow * 128 + unit * 8);
            } else {
                const float4* p = (const float4*)(A32 + (size_t)grow * 128 + unit * 8);
                float4 a0 = p[0], a1 = p[1];
                hp[0] = __floats2half2_rn(a0.x, a0.y);
                hp[1] = __floats2half2_rn(a0.z, a0.w);
                hp[2] = __floats2half2_rn(a1.x, a1.y);
                hp[3] = __floats2half2_rn(a1.z, a1.w);
            }
        }
        if (abias) {
            const float4* b = (const float4*)(abias + unit * 8);
            float4 b0 = b[0], b1 = b[1];
            float bb[8];
            bb[0] = b0.x; bb[1] = b0.y; bb[2] = b0.z; bb[3] = b0.w;
            bb[4] = b1.x; bb[5] = b1.y; bb[6] = b1.z; bb[7] = b1.w;
#pragma unroll
            for (int j = 0; j < 4; j++) {
                float2 f = __half22float2(hp[j]);
                f.x = fmaxf(f.x + bb[2 * j], 0.f);
                f.y = fmaxf(f.y + bb[2 * j + 1], 0.f);
                hp[j] = __floats2half2_rn(f.x, f.y);
            }
        }
        *(uint4*)(smem + A_OF + (unsigned int)row * PADB + (unsigned int)unit * 16) = u;
    }

    // ---- W tile
    for (int i = tid; i < BN * 16; i += 256) {
        int row = i >> 4;
        int unit = i & 15;
        *(uint4*)(smem + B_OF + (unsigned int)row * PADB + (unsigned int)unit * 16) =
            ((const uint4*)Wf)[row * 16 + unit];
    }
    __syncthreads();

    const int g  = lane >> 2;
    const int tg = lane & 3;
    float acc[2][NT][4];
#pragma unroll
    for (int mt = 0; mt < 2; mt++)
#pragma unroll
        for (int nt = 0; nt < NT; nt++)
#pragma unroll
            for (int j = 0; j < 4; j++) acc[mt][nt][j] = 0.f;

#pragma unroll
    for (int ks = 0; ks < 8; ks++) {
        const unsigned int kb = (unsigned int)(ks * 16 + tg * 2) * 2;
        unsigned int a[2][4];
#pragma unroll
        for (int mt = 0; mt < 2; mt++) {
            unsigned int ro = A_OF + (unsigned int)(wr * 32 + mt * 16 + g) * PADB + kb;
            a[mt][0] = *(const unsigned int*)(smem + ro);
            a[mt][1] = *(const unsigned int*)(smem + ro + 8 * PADB);
            a[mt][2] = *(const unsigned int*)(smem + ro + 16);
            a[mt][3] = *(const unsigned int*)(smem + ro + 8 * PADB + 16);
        }
#pragma unroll
        for (int nt = 0; nt < NT; nt++) {
            unsigned int no = B_OF + (unsigned int)(wc * NT * 8 + nt * 8 + g) * PADB + kb;
            unsigned int b[2];
            b[0] = *(const unsigned int*)(smem + no);
            b[1] = *(const unsigned int*)(smem + no + 16);
#pragma unroll
            for (int mt = 0; mt < 2; mt++)
                mma_f16(acc[mt][nt], a[mt], b);
        }
    }

    if (C8) {
        // ---- int8 message quant epilogue
        __syncthreads();
        float* rmax = (float*)smem;
        if (tid < 128) rmax[tid] = 0.f;
        __syncthreads();
#pragma unroll
        for (int mt = 0; mt < 2; mt++) {
            int lr = wr * 32 + mt * 16 + g;
            float m0 = 0.f, m1 = 0.f;
#pragma unroll
            for (int nt = 0; nt < NT; nt++) {
                m0 = fmaxf(m0, fmaxf(fabsf(acc[mt][nt][0]), fabsf(acc[mt][nt][1])));
                m1 = fmaxf(m1, fmaxf(fabsf(acc[mt][nt][2]), fabsf(acc[mt][nt][3])));
            }
            atomicMax((int*)&rmax[lr], __float_as_int(m0));
            atomicMax((int*)&rmax[lr + 8], __float_as_int(m1));
        }
        __syncthreads();
#pragma unroll
        for (int mt = 0; mt < 2; mt++) {
            int lr = wr * 32 + mt * 16 + g;
            int grow = row0 + lr;
            float M0 = rmax[lr], M1 = rmax[lr + 8];
            float q0 = (M0 > 0.f) ? 127.f / M0 : 0.f;
            float q1 = (M1 > 0.f) ? 127.f / M1 : 0.f;
            if (wc == 0 && tg == 0) {
                if (grow < n)     Csc[grow]     = M0 * g_dinv[grow] * (1.f / 127.f);
                if (grow + 8 < n) Csc[grow + 8] = M1 * g_dinv[grow + 8] * (1.f / 127.f);
            }
#pragma unroll
            for (int nt = 0; nt < NT; nt++) {
                int col = wc * NT * 8 + nt * 8 + tg * 2;
                if (grow < n) {
                    int b0 = __float2int_rn(acc[mt][nt][0] * q0);
                    int b1 = __float2int_rn(acc[mt][nt][1] * q0);
                    *(unsigned short*)(C8 + (size_t)grow * 128 + col) =
                        (unsigned short)(((b1 & 0xff) << 8) | (b0 & 0xff));
                }
                if (grow + 8 < n) {
                    int b2 = __float2int_rn(acc[mt][nt][2] * q1);
                    int b3 = __float2int_rn(acc[mt][nt][3] * q1);
                    *(unsigned short*)(C8 + (size_t)(grow + 8) * 128 + col) =
                        (unsigned short)(((b3 & 0xff) << 8) | (b2 & 0xff));
                }
            }
        }
    } else if (C16) {
        // ---- fp16 out (+cbias)
#pragma unroll
        for (int mt = 0; mt < 2; mt++) {
            int r0i = row0 + wr * 32 + mt * 16 + g;
#pragma unroll
            for (int nt = 0; nt < NT; nt++) {
                int col = wc * NT * 8 + nt * 8 + tg * 2;
                float b0 = cbias[col], b1 = cbias[col + 1];
                if (r0i < n)
                    *(__half2*)(C16 + (size_t)r0i * BN + col) =
                        __floats2half2_rn(acc[mt][nt][0] + b0, acc[mt][nt][1] + b1);
                if (r0i + 8 < n)
                    *(__half2*)(C16 + (size_t)(r0i + 8) * BN + col) =
                        __floats2half2_rn(acc[mt][nt][2] + b0, acc[mt][nt][3] + b1);
            }
        }
    } else {
        // ---- fused log_softmax epilogue (BN == 64): full row in this block
        __syncthreads();
        float* sx = (float*)smem;   // 128 rows x stride 68 floats (= PADB bytes)
#pragma unroll
        for (int mt = 0; mt < 2; mt++) {
            int lr = wr * 32 + mt * 16 + g;
#pragma unroll
            for (int nt = 0; nt < NT; nt++) {
                int col = wc * NT * 8 + nt * 8 + tg * 2;
                float b0 = cbias[col], b1 = cbias[col + 1];
                *(float2*)(sx + lr * 68 + col) =
                    make_float2(acc[mt][nt][0] + b0, acc[mt][nt][1] + b1);
                *(float2*)(sx + (lr + 8) * 68 + col) =
                    make_float2(acc[mt][nt][2] + b0, acc[mt][nt][3] + b1);
            }
        }
        __syncthreads();
        for (int r = wid * 16; r < wid * 16 + 16; r++) {
            int grow = row0 + r;
            if (grow >= n) break;
            float v0 = sx[r * 68 + lane];
            float v1 = sx[r * 68 + lane + 32];
            float m = fmaxf(v0, v1);
#pragma unroll
            for (int o = 16; o > 0; o >>= 1)
                m = fmaxf(m, __shfl_xor_sync(0xFFFFFFFFu, m, o));
            float s = expf(v0 - m) + expf(v1 - m);
#pragma unroll
            for (int o = 16; o > 0; o >>= 1)
                s += __shfl_xor_sync(0xFFFFFFFFu, s, o);
            float lg = m + logf(s);
            osm[(size_t)grow * 64 + lane]      = v0 - lg;
            osm[(size_t)grow * 64 + lane + 32] = v1 - lg;
        }
    }
}

__global__ void __launch_bounds__(256, 2)
k_gemm128(const float* A32, const __half* A16, const float* abias,
          const __half* Wf, const float* cbias,
          signed char* C8, float* Csc, __half* C16, int n)
{
    extern __shared__ __align__(16) char smem_dyn[];
    gemm_body<128>(A32, A16, abias, Wf, cbias, C8, Csc, C16, 0, n, smem_dyn);
}

__global__ void __launch_bounds__(256, 2)
k_gemm64s(const __half* A16, const __half* Wf, const float* cbias,
          float* osm, int n)
{
    extern __shared__ __align__(16) char smem_dyn[];
    gemm_body<64>(0, A16, 0, Wf, cbias, 0, 0, 0, osm, n, smem_dyn);
}

// ---------------- CSR pull-gather (uint2, 2 rows/load, 4 loads in flight) --
__device__ __forceinline__ void addq(float* a, uint2 u, float sc) {
    a[0] = fmaf(sc, (float)(signed char)(u.x), a[0]);
    a[1] = fmaf(sc, (float)(signed char)(u.x >> 8), a[1]);
    a[2] = fmaf(sc, (float)(signed char)(u.x >> 16), a[2]);
    a[3] = fmaf(sc, (float)(signed char)(u.x >> 24), a[3]);
    a[4] = fmaf(sc, (float)(signed char)(u.y), a[4]);
    a[5] = fmaf(sc, (float)(signed char)(u.y >> 8), a[5]);
    a[6] = fmaf(sc, (float)(signed char)(u.y >> 16), a[6]);
    a[7] = fmaf(sc, (float)(signed char)(u.y >> 24), a[7]);
}

__launch_bounds__(256)
__global__ void k_gather(const uint2* __restrict__ M8,   // row = 16 uint2
                         const float* __restrict__ sc,
                         uint4* __restrict__ H16, int n)  // row = 16 uint4
{
    int warp = (blockIdx.x * blockDim.x + threadIdx.x) >> 5;
    int lane = threadIdx.x & 31;
    if (warp >= n) return;
    int half = lane >> 4;
    int sub  = lane & 15;
    int beg = g_off[warp];
    int total = g_off[warp + 1] - beg + 1;   // +1 self loop (virtual idx 0)

    float acc[8];
#pragma unroll
    for (int k = 0; k < 8; k++) acc[k] = 0.f;

    for (int base = 0; base < total; base += 32) {
        int cnt = total - base;
        if (cnt > 32) cnt = 32;
        int vj = base + lane;
        int idx = 0;
        if (lane < cnt) idx = (vj == 0) ? warp : g_csr[beg + vj - 1];
        int j = 0;
        for (; j + 8 <= cnt; j += 8) {
            int s0 = __shfl_sync(0xFFFFFFFFu, idx, j + half);
            int s1 = __shfl_sync(0xFFFFFFFFu, idx, j + 2 + half);
            int s2 = __shfl_sync(0xFFFFFFFFu, idx, j + 4 + half);
            int s3 = __shfl_sync(0xFFFFFFFFu, idx, j + 6 + half);
            uint2 u0 = M8[(size_t)s0 * 16 + sub];
            float f0 = sc[s0];
            uint2 u1 = M8[(size_t)s1 * 16 + sub];
            float f1 = sc[s1];
            uint2 u2 = M8[(size_t)s2 * 16 + sub];
            float f2 = sc[s2];
            uint2 u3 = M8[(size_t)s3 * 16 + sub];
            float f3 = sc[s3];
            addq(acc, u0, f0);
            addq(acc, u1, f1);
            addq(acc, u2, f2);
            addq(acc, u3, f3);
        }
        if (j + 4 <= cnt) {
            int s0 = __shfl_sync(0xFFFFFFFFu, idx, j + half);
            int s1 = __shfl_sync(0xFFFFFFFFu, idx, j + 2 + half);
            uint2 u0 = M8[(size_t)s0 * 16 + sub];
            float f0 = sc[s0];
            uint2 u1 = M8[(size_t)s1 * 16 + sub];
            float f1 = sc[s1];
            addq(acc, u0, f0);
            addq(acc, u1, f1);
            j += 4;
        }
        if (j + 2 <= cnt) {
            int s = __shfl_sync(0xFFFFFFFFu, idx, j + half);
            uint2 u = M8[(size_t)s * 16 + sub];
            addq(acc, u, sc[s]);
            j += 2;
        }
        if (j < cnt) {
            int s = __shfl_sync(0xFFFFFFFFu, idx, j);
            if (half == 0) {
                uint2 u = M8[(size_t)s * 16 + sub];
                addq(acc, u, sc[s]);
            }
        }
    }

#pragma unroll
    for (int k = 0; k < 8; k++)
        acc[k] += __shfl_down_sync(0xFFFFFFFFu, acc[k], 16);

    if (half == 0) {
        float di = g_dinv[warp];
        uint4 o;
        __half2* oh = (__half2*)&o;
#pragma unroll
        for (int i = 0; i < 4; i++)
            oh[i] = __floats2half2_rn(acc[2 * i] * di, acc[2 * i + 1] * di);
        H16[(size_t)warp * 16 + sub] = o;
    }
}

// ---------------- host launcher ---------------------------------------------
extern "C" void kernel_launch(void* const* d_in, const int* in_sizes, int n_in,
                              void* d_out, int out_size)
{
    const float* x   = (const float*)d_in[0];
    const int*   ei  = (const int*)d_in[1];
    const float* W0  = (const float*)d_in[2];
    const float* b0  = (const float*)d_in[3];
    const float* W1  = (const float*)d_in[4];
    const float* b1  = (const float*)d_in[5];
    const float* W2  = (const float*)d_in[6];
    const float* b2  = (const float*)d_in[7];
    const float* W3  = (const float*)d_in[8];
    const float* b3  = (const float*)d_in[9];
    const float* Wm1 = (const float*)d_in[10];
    const float* bm1 = (const float*)d_in[11];
    const float* Wm2 = (const float*)d_in[12];
    const float* bm2 = (const float*)d_in[13];
    float* out = (float*)d_out;

    const int n = in_sizes[0] / DIM;      // 100000
    const int e = in_sizes[1] / 2;        // 1600000
    const int* src = ei;
    const int* dst = ei + e;

    signed char* M8 = 0;
    float* Sc = 0;
    __half* H16 = 0;
    __half* F16 = 0;
    __half* Wf = 0;
    cudaGetSymbolAddress((void**)&M8,  g_M8);
    cudaGetSymbolAddress((void**)&Sc,  g_sc);
    cudaGetSymbolAddress((void**)&H16, g_H16);
    cudaGetSymbolAddress((void**)&F16, g_F16);
    cudaGetSymbolAddress((void**)&Wf,  g_Wf);

    const int SM128 = 128 * PADB + 128 * PADB;   // 69632
    const int SM64  = 128 * PADB + 64 * PADB;    // 52224
    cudaFuncSetAttribute(k_gemm128, cudaFuncAttributeMaxDynamicSharedMemorySize, SM128);
    cudaFuncSetAttribute(k_gemm64s, cudaFuncAttributeMaxDynamicSharedMemorySize, SM64);

    // side stream + fork/join events (created once on the first — correctness —
    // call, which happens outside graph capture; during capture only the event
    // edges are recorded, producing parallel graph branches)
    static cudaStream_t s2 = 0;
    static cudaEvent_t evF = 0, evD = 0, evB = 0;
    if (!s2) {
        cudaStreamCreateWithFlags(&s2, cudaStreamNonBlocking);
        cudaEventCreateWithFlags(&evF, cudaEventDisableTiming);
        cudaEventCreateWithFlags(&evD, cudaEventDisableTiming);
        cudaEventCreateWithFlags(&evB, cudaEventDisableTiming);
    }

    const int nscanb = (n + SCHUNK - 1) / SCHUNK;
    const int gblocks = (n + 127) / 128;                 // 782
    const int gatherb = (n * 32 + 255) / 256;            // 12500

    // ---- fork: side branch gets weight convert (independent) ----
    cudaEventRecord(evF, 0);
    cudaStreamWaitEvent(s2, evF, 0);
    k_convW_all<<<(WTOT + 255) / 256, 256, 0, s2>>>(W0, W1, W2, W3, Wm1, Wm2);

    // ---- main branch: degrees -> dinv ----
    k_zero<<<(n + 255) / 256, 256>>>(n);
    k_count<<<(e + 255) / 256, 256>>>(dst, e);
    k_bsum<<<nscanb, SCHUNK>>>(n);           // also computes dinv
    cudaEventRecord(evD, 0);

    // side branch: layer-0 GEMM (needs Wf slot 0 + dinv + x only)
    cudaStreamWaitEvent(s2, evD, 0);
    k_gemm128<<<gblocks, 256, SM128, s2>>>(x, 0, 0, Wf + 0 * WSLOT, 0, M8, Sc, 0, n);
    cudaEventRecord(evB, s2);

    // main branch: CSR build (overlaps with gemm0 on s2)
    k_bscan<<<1, 128>>>(nscanb);
    k_offsets<<<nscanb, SCHUNK>>>(n);        // also preloads g_cur = g_off
    k_fill<<<(e + 255) / 256, 256>>>(src, dst, e);

    // ---- join: gather0 needs CSR (main) + messages (s2) ----
    cudaStreamWaitEvent(0, evB, 0);
    k_gather<<<gatherb, 256>>>((const uint2*)M8, Sc, (uint4*)H16, n);

    // ---- layers 1-3 ----
    k_gemm128<<<gblocks, 256, SM128>>>(0, H16, b0, Wf + 1 * WSLOT, 0, M8, Sc, 0, n);
    k_gather<<<gatherb, 256>>>((const uint2*)M8, Sc, (uint4*)H16, n);

    k_gemm128<<<gblocks, 256, SM128>>>(0, H16, b1, Wf + 2 * WSLOT, 0, M8, Sc, 0, n);
    k_gather<<<gatherb, 256>>>((const uint2*)M8, Sc, (uint4*)H16, n);

    k_gemm128<<<gblocks, 256, SM128>>>(0, H16, b2, Wf + 3 * WSLOT, 0, M8, Sc, 0, n);
    k_gather<<<gatherb, 256>>>((const uint2*)M8, Sc, (uint4*)H16, n);

    // ---- MLP1: F16 = half(relu(H16 + b3) @ Wm1 + bm1) ----
    k_gemm128<<<gblocks, 256, SM128>>>(0, H16, b3, Wf + 4 * WSLOT, bm1, 0, 0, F16, n);

    // ---- MLP2 + fused log_softmax -> out ----
    k_gemm64s<<<gblocks, 256, SM64>>>(F16, Wf + 5 * WSLOT, bm2, out, n);
}

// round 14
// speedup vs baseline: 1.8257x; 1.2157x over previous
#include <cuda_runtime.h>
#include <cuda_fp16.h>
#include <cstdint>
#include <stdint.h>
#include <math.h>

// Problem constants (fixed by the dataset)
#define N_NODES 100000
#define N_EDGES 1600000
#define DIM 128
#define ODIM 64
#define WSLOT 16384
#define WTOT (5 * WSLOT + ODIM * DIM)
#define PADB 272   // smem row stride in bytes, multiple of 16, conflict-free
#define SCHUNK 1024

// ---------------- scratch (static device globals; no allocation) -----------
__device__ unsigned char g_M8[(size_t)N_NODES * DIM]; // fp8-e4m3 messages
__device__ __half       g_sch[N_NODES];               // per-row dequant scale (fp16)
__device__ __half       g_H16[(size_t)N_NODES * DIM]; // fp16 aggregated features
__device__ __half       g_F16[(size_t)N_NODES * DIM]; // fp16 MLP intermediate
__device__ int          g_deg[N_NODES];
__device__ int          g_cur[N_NODES];
__device__ int          g_off[N_NODES + 1];
__device__ int          g_csr[N_EDGES];
__device__ int          g_bsum[128];
__device__ float        g_dinv[N_NODES];
__device__ __half       g_Wf[WTOT];                   // fp16 transposed weights [N][K]

// ---------------- mma.sync fp16 helper (baseline PTX) ----------------------
__device__ __forceinline__ void mma_f16(float* c, const unsigned int* a,
                                        const unsigned int* b) {
    asm volatile(
        "mma.sync.aligned.m16n8k16.row.col.f32.f16.f16.f32 "
        "{%0,%1,%2,%3}, {%4,%5,%6,%7}, {%8,%9}, {%0,%1,%2,%3};"
        : "+f"(c[0]), "+f"(c[1]), "+f"(c[2]), "+f"(c[3])
        : "r"(a[0]), "r"(a[1]), "r"(a[2]), "r"(a[3]), "r"(b[0]), "r"(b[1]));
}

// fp8 pack/unpack (baseline PTX, sm_89+, valid at compute_100)
__device__ __forceinline__ unsigned short f32x2_to_e4m3x2(float hi, float lo) {
    unsigned short us;
    asm("cvt.rn.satfinite.e4m3x2.f32 %0, %1, %2;" : "=h"(us) : "f"(hi), "f"(lo));
    return us;   // byte0 = lo, byte1 = hi
}
__device__ __forceinline__ __half2 e4m3x2_to_h2(unsigned short w) {
    unsigned int r;
    asm("cvt.rn.f16x2.e4m3x2 %0, %1;" : "=r"(r) : "h"(w));
    return *(__half2*)&r;
}

// ---------------- setup kernels --------------------------------------------
__global__ void k_zero(int n) {
    int i = blockIdx.x * blockDim.x + threadIdx.x;
    if (i < n) g_deg[i] = 0;
}
__global__ void k_count(const int* __restrict__ dst, int e) {
    int i = blockIdx.x * blockDim.x + threadIdx.x;
    if (i < e) atomicAdd(&g_deg[dst[i]], 1);
}
__global__ void k_bsum(int n) {            // block sums + dinv (deg final here)
    __shared__ int sh[SCHUNK];
    int i = blockIdx.x * SCHUNK + threadIdx.x;
    int d = (i < n) ? g_deg[i] : 0;
    if (i < n) g_dinv[i] = rsqrtf((float)(d + 1));
    sh[threadIdx.x] = d;
    __syncthreads();
    for (int off = SCHUNK / 2; off > 0; off >>= 1) {
        if (threadIdx.x < off) sh[threadIdx.x] += sh[threadIdx.x + off];
        __syncthreads();
    }
    if (threadIdx.x == 0) g_bsum[blockIdx.x] = sh[0];
}
__global__ void k_bscan(int nb) {
    __shared__ int sh[128];
    int v = (threadIdx.x < nb) ? g_bsum[threadIdx.x] : 0;
    sh[threadIdx.x] = v;
    __syncthreads();
    for (int off = 1; off < 128; off <<= 1) {
        int t = (threadIdx.x >= off) ? sh[threadIdx.x - off] : 0;
        __syncthreads();
        sh[threadIdx.x] += t;
        __syncthreads();
    }
    if (threadIdx.x < nb) g_bsum[threadIdx.x] = sh[threadIdx.x] - v;
}
__global__ void k_offsets(int n) {
    __shared__ int sh[SCHUNK];
    int i = blockIdx.x * SCHUNK + threadIdx.x;
    int v = (i < n) ? g_deg[i] : 0;
    sh[threadIdx.x] = v;
    __syncthreads();
    for (int off = 1; off < SCHUNK; off <<= 1) {
        int t = (threadIdx.x >= off) ? sh[threadIdx.x - off] : 0;
        __syncthreads();
        sh[threadIdx.x] += t;
        __syncthreads();
    }
    int excl = g_bsum[blockIdx.x] + sh[threadIdx.x] - v;
    if (i < n) { g_off[i] = excl; g_cur[i] = excl; }   // cur preloaded as cursor
    if (i == n - 1) g_off[n] = excl + v;
}
__global__ void k_fill(const int* __restrict__ src, const int* __restrict__ dst, int e) {
    int i = blockIdx.x * blockDim.x + threadIdx.x;
    if (i < e) {
        int pos = atomicAdd(&g_cur[dst[i]], 1);
        g_csr[pos] = src[i];
    }
}
__global__ void k_convW_all(const float* __restrict__ W0, const float* __restrict__ W1,
                            const float* __restrict__ W2, const float* __restrict__ W3,
                            const float* __restrict__ Wm1, const float* __restrict__ Wm2) {
    int i = blockIdx.x * blockDim.x + threadIdx.x;
    if (i >= WTOT) return;
    int slot = i >> 14;
    int j = i & 16383;
    const float* W;
    int N;
    switch (slot) {
        case 0:  W = W0;  N = 128; break;
        case 1:  W = W1;  N = 128; break;
        case 2:  W = W2;  N = 128; break;
        case 3:  W = W3;  N = 128; break;
        case 4:  W = Wm1; N = 128; break;
        default: W = Wm2; N = 64;  break;
    }
    const int K = 128;
    int nrow = j / K;
    int k = j % K;
    g_Wf[i] = __float2half_rn(W[k * N + nrow]);
}

// ---------------- fp16 HMMA GEMM body ----------------------------------------
// acc = act(A) @ W; act = relu(a+abias) if abias. fp32 accum.
// Modes: C8 != 0 -> fp8-e4m3 message quant (Csc = M*dinv/240, fp16)
//        C16 != 0 -> fp16 out = half(acc + cbias)
//        else     -> fused log_softmax over BN cols -> osm (fp32)
template <int BN>
__device__ __forceinline__ void gemm_body(const float* __restrict__ A32,
                                          const __half* __restrict__ A16,
                                          const float* __restrict__ abias,
                                          const __half* __restrict__ Wf,
                                          const float* __restrict__ cbias,
                                          unsigned char* __restrict__ C8,
                                          __half* __restrict__ Csc,
                                          __half* __restrict__ C16,
                                          float* __restrict__ osm,
                                          int n, char* smem)
{
    constexpr int NT = BN / 16;
    const unsigned int A_OF = 0;
    const unsigned int B_OF = 128 * PADB;

    const int tid  = threadIdx.x;
    const int wid  = tid >> 5;
    const int lane = tid & 31;
    const int wr   = wid >> 1;
    const int wc   = wid & 1;
    const int row0 = blockIdx.x * 128;

    // ---- A tile -> fp16 smem, fused relu(+abias)
    for (int i = tid; i < 128 * 16; i += 256) {
        int row = i >> 4;
        int unit = i & 15;
        int grow = row0 + row;
        uint4 u = make_uint4(0, 0, 0, 0);
        __half2* hp = (__half2*)&u;
        if (grow < n) {
            if (A16) {
                u = *(const uint4*)(A16 + (size_t)grow * 128 + unit * 8);
            } else {
                const float4* p = (const float4*)(A32 + (size_t)grow * 128 + unit * 8);
                float4 a0 = p[0], a1 = p[1];
                hp[0] = __floats2half2_rn(a0.x, a0.y);
                hp[1] = __floats2half2_rn(a0.z, a0.w);
                hp[2] = __floats2half2_rn(a1.x, a1.y);
                hp[3] = __floats2half2_rn(a1.z, a1.w);
            }
        }
        if (abias) {
            const float4* b = (const float4*)(abias + unit * 8);
            float4 b0 = b[0], b1 = b[1];
            float bb[8];
            bb[0] = b0.x; bb[1] = b0.y; bb[2] = b0.z; bb[3] = b0.w;
            bb[4] = b1.x; bb[5] = b1.y; bb[6] = b1.z; bb[7] = b1.w;
#pragma unroll
            for (int j = 0; j < 4; j++) {
                float2 f = __half22float2(hp[j]);
                f.x = fmaxf(f.x + bb[2 * j], 0.f);
                f.y = fmaxf(f.y + bb[2 * j + 1], 0.f);
                hp[j] = __floats2half2_rn(f.x, f.y);
            }
        }
        *(uint4*)(smem + A_OF + (unsigned int)row * PADB + (unsigned int)unit * 16) = u;
    }

    // ---- W tile
    for (int i = tid; i < BN * 16; i += 256) {
        int row = i >> 4;
        int unit = i & 15;
        *(uint4*)(smem + B_OF + (unsigned int)row * PADB + (unsigned int)unit * 16) =
            ((const uint4*)Wf)[row * 16 + unit];
    }
    __syncthreads();

    const int g  = lane >> 2;
    const int tg = lane & 3;
    float acc[2][NT][4];
#pragma unroll
    for (int mt = 0; mt < 2; mt++)
#pragma unroll
        for (int nt = 0; nt < NT; nt++)
#pragma unroll
            for (int j = 0; j < 4; j++) acc[mt][nt][j] = 0.f;

#pragma unroll
    for (int ks = 0; ks < 8; ks++) {
        const unsigned int kb = (unsigned int)(ks * 16 + tg * 2) * 2;
        unsigned int a[2][4];
#pragma unroll
        for (int mt = 0; mt < 2; mt++) {
            unsigned int ro = A_OF + (unsigned int)(wr * 32 + mt * 16 + g) * PADB + kb;
            a[mt][0] = *(const unsigned int*)(smem + ro);
            a[mt][1] = *(const unsigned int*)(smem + ro + 8 * PADB);
            a[mt][2] = *(const unsigned int*)(smem + ro + 16);
            a[mt][3] = *(const unsigned int*)(smem + ro + 8 * PADB + 16);
        }
#pragma unroll
        for (int nt = 0; nt < NT; nt++) {
            unsigned int no = B_OF + (unsigned int)(wc * NT * 8 + nt * 8 + g) * PADB + kb;
            unsigned int b[2];
            b[0] = *(const unsigned int*)(smem + no);
            b[1] = *(const unsigned int*)(smem + no + 16);
#pragma unroll
            for (int mt = 0; mt < 2; mt++)
                mma_f16(acc[mt][nt], a[mt], b);
        }
    }

    if (C8) {
        // ---- fp8-e4m3 message quant epilogue
        __syncthreads();
        float* rmax = (float*)smem;
        if (tid < 128) rmax[tid] = 0.f;
        __syncthreads();
#pragma unroll
        for (int mt = 0; mt < 2; mt++) {
            int lr = wr * 32 + mt * 16 + g;
            float m0 = 0.f, m1 = 0.f;
#pragma unroll
            for (int nt = 0; nt < NT; nt++) {
                m0 = fmaxf(m0, fmaxf(fabsf(acc[mt][nt][0]), fabsf(acc[mt][nt][1])));
                m1 = fmaxf(m1, fmaxf(fabsf(acc[mt][nt][2]), fabsf(acc[mt][nt][3])));
            }
            atomicMax((int*)&rmax[lr], __float_as_int(m0));
            atomicMax((int*)&rmax[lr + 8], __float_as_int(m1));
        }
        __syncthreads();
#pragma unroll
        for (int mt = 0; mt < 2; mt++) {
            int lr = wr * 32 + mt * 16 + g;
            int grow = row0 + lr;
            float M0 = rmax[lr], M1 = rmax[lr + 8];
            float q0 = (M0 > 0.f) ? 240.f / M0 : 0.f;
            float q1 = (M1 > 0.f) ? 240.f / M1 : 0.f;
            if (wc == 0 && tg == 0) {
                if (grow < n)
                    Csc[grow] = __float2half_rn(M0 * g_dinv[grow] * (1.f / 240.f));
                if (grow + 8 < n)
                    Csc[grow + 8] = __float2half_rn(M1 * g_dinv[grow + 8] * (1.f / 240.f));
            }
#pragma unroll
            for (int nt = 0; nt < NT; nt++) {
                int col = wc * NT * 8 + nt * 8 + tg * 2;
                if (grow < n) {
                    *(unsigned short*)(C8 + (size_t)grow * 128 + col) =
                        f32x2_to_e4m3x2(acc[mt][nt][1] * q0, acc[mt][nt][0] * q0);
                }
                if (grow + 8 < n) {
                    *(unsigned short*)(C8 + (size_t)(grow + 8) * 128 + col) =
                        f32x2_to_e4m3x2(acc[mt][nt][3] * q1, acc[mt][nt][2] * q1);
                }
            }
        }
    } else if (C16) {
        // ---- fp16 out (+cbias)
#pragma unroll
        for (int mt = 0; mt < 2; mt++) {
            int r0i = row0 + wr * 32 + mt * 16 + g;
#pragma unroll
            for (int nt = 0; nt < NT; nt++) {
                int col = wc * NT * 8 + nt * 8 + tg * 2;
                float b0 = cbias[col], b1 = cbias[col + 1];
                if (r0i < n)
                    *(__half2*)(C16 + (size_t)r0i * BN + col) =
                        __floats2half2_rn(acc[mt][nt][0] + b0, acc[mt][nt][1] + b1);
                if (r0i + 8 < n)
                    *(__half2*)(C16 + (size_t)(r0i + 8) * BN + col) =
                        __floats2half2_rn(acc[mt][nt][2] + b0, acc[mt][nt][3] + b1);
            }
        }
    } else {
        // ---- fused log_softmax epilogue (BN == 64): full row in this block
        __syncthreads();
        float* sx = (float*)smem;   // 128 rows x stride 68 floats (= PADB bytes)
#pragma unroll
        for (int mt = 0; mt < 2; mt++) {
            int lr = wr * 32 + mt * 16 + g;
#pragma unroll
            for (int nt = 0; nt < NT; nt++) {
                int col = wc * NT * 8 + nt * 8 + tg * 2;
                float b0 = cbias[col], b1 = cbias[col + 1];
                *(float2*)(sx + lr * 68 + col) =
                    make_float2(acc[mt][nt][0] + b0, acc[mt][nt][1] + b1);
                *(float2*)(sx + (lr + 8) * 68 + col) =
                    make_float2(acc[mt][nt][2] + b0, acc[mt][nt][3] + b1);
            }
        }
        __syncthreads();
        for (int r = wid * 16; r < wid * 16 + 16; r++) {
            int grow = row0 + r;
            if (grow >= n) break;
            float v0 = sx[r * 68 + lane];
            float v1 = sx[r * 68 + lane + 32];
            float m = fmaxf(v0, v1);
#pragma unroll
            for (int o = 16; o > 0; o >>= 1)
                m = fmaxf(m, __shfl_xor_sync(0xFFFFFFFFu, m, o));
            float s = expf(v0 - m) + expf(v1 - m);
#pragma unroll
            for (int o = 16; o > 0; o >>= 1)
                s += __shfl_xor_sync(0xFFFFFFFFu, s, o);
            float lg = m + logf(s);
            osm[(size_t)grow * 64 + lane]      = v0 - lg;
            osm[(size_t)grow * 64 + lane + 32] = v1 - lg;
        }
    }
}

__global__ void __launch_bounds__(256, 2)
k_gemm128(const float* A32, const __half* A16, const float* abias,
          const __half* Wf, const float* cbias,
          unsigned char* C8, __half* Csc, __half* C16, int n)
{
    extern __shared__ __align__(16) char smem_dyn[];
    gemm_body<128>(A32, A16, abias, Wf, cbias, C8, Csc, C16, 0, n, smem_dyn);
}

__global__ void __launch_bounds__(256, 2)
k_gemm64s(const __half* A16, const __half* Wf, const float* cbias,
          float* osm, int n)
{
    extern __shared__ __align__(16) char smem_dyn[];
    gemm_body<64>(0, A16, 0, Wf, cbias, 0, 0, 0, osm, n, smem_dyn);
}

// ---------------- CSR pull-gather (fp8 rows, uint2, 2 rows/load) -----------
// H16[d] = half( dinv[d] * sum_{s in N(d) U {d}} sc[s] * M8[s] )
// Row = 128 fp8 = 16 uint2; lanes 0-15 neighbor j, lanes 16-31 neighbor j+1.
// Decode: cvt e4m3x2->f16x2, HFMA2 with half2(scale), fp16 accumulators.
__device__ __forceinline__ void addq8(__half2* a, uint2 u, __half2 s) {
    a[0] = __hfma2(e4m3x2_to_h2((unsigned short)(u.x)), s, a[0]);
    a[1] = __hfma2(e4m3x2_to_h2((unsigned short)(u.x >> 16)), s, a[1]);
    a[2] = __hfma2(e4m3x2_to_h2((unsigned short)(u.y)), s, a[2]);
    a[3] = __hfma2(e4m3x2_to_h2((unsigned short)(u.y >> 16)), s, a[3]);
}
__device__ __forceinline__ __half2 dup_from_bits(unsigned int b) {
    return __half2half2(__ushort_as_half((unsigned short)b));
}

__launch_bounds__(256)
__global__ void k_gather(const uint2* __restrict__ M8,   // row = 16 uint2
                         const __half* __restrict__ sch,
                         uint4* __restrict__ H16, int n)  // row = 16 uint4
{
    int warp = (blockIdx.x * blockDim.x + threadIdx.x) >> 5;
    int lane = threadIdx.x & 31;
    if (warp >= n) return;
    int half = lane >> 4;
    int sub  = lane & 15;
    int beg = g_off[warp];
    int total = g_off[warp + 1] - beg + 1;   // +1 self loop (virtual idx 0)

    __half2 acc[4];
#pragma unroll
    for (int k = 0; k < 4; k++) acc[k] = __half2half2(__ushort_as_half(0));

    for (int base = 0; base < total; base += 32) {
        int cnt = total - base;
        if (cnt > 32) cnt = 32;
        int vj = base + lane;
        int idx = 0;
        unsigned int scb = 0;
        if (lane < cnt) {
            idx = (vj == 0) ? warp : g_csr[beg + vj - 1];
            scb = (unsigned int)__half_as_ushort(sch[idx]);
        }
        int j = 0;
        for (; j + 8 <= cnt; j += 8) {
            int s0 = __shfl_sync(0xFFFFFFFFu, idx, j + half);
            int s1 = __shfl_sync(0xFFFFFFFFu, idx, j + 2 + half);
            int s2 = __shfl_sync(0xFFFFFFFFu, idx, j + 4 + half);
            int s3 = __shfl_sync(0xFFFFFFFFu, idx, j + 6 + half);
            unsigned int c0 = __shfl_sync(0xFFFFFFFFu, scb, j + half);
            unsigned int c1 = __shfl_sync(0xFFFFFFFFu, scb, j + 2 + half);
            unsigned int c2 = __shfl_sync(0xFFFFFFFFu, scb, j + 4 + half);
            unsigned int c3 = __shfl_sync(0xFFFFFFFFu, scb, j + 6 + half);
            uint2 u0 = M8[(size_t)s0 * 16 + sub];
            uint2 u1 = M8[(size_t)s1 * 16 + sub];
            uint2 u2 = M8[(size_t)s2 * 16 + sub];
            uint2 u3 = M8[(size_t)s3 * 16 + sub];
            addq8(acc, u0, dup_from_bits(c0));
            addq8(acc, u1, dup_from_bits(c1));
            addq8(acc, u2, dup_from_bits(c2));
            addq8(acc, u3, dup_from_bits(c3));
        }
        if (j + 4 <= cnt) {
            int s0 = __shfl_sync(0xFFFFFFFFu, idx, j + half);
            int s1 = __shfl_sync(0xFFFFFFFFu, idx, j + 2 + half);
            unsigned int c0 = __shfl_sync(0xFFFFFFFFu, scb, j + half);
            unsigned int c1 = __shfl_sync(0xFFFFFFFFu, scb, j + 2 + half);
            uint2 u0 = M8[(size_t)s0 * 16 + sub];
            uint2 u1 = M8[(size_t)s1 * 16 + sub];
            addq8(acc, u0, dup_from_bits(c0));
            addq8(acc, u1, dup_from_bits(c1));
            j += 4;
        }
        if (j + 2 <= cnt) {
            int s = __shfl_sync(0xFFFFFFFFu, idx, j + half);
            unsigned int c = __shfl_sync(0xFFFFFFFFu, scb, j + half);
            uint2 u = M8[(size_t)s * 16 + sub];
            addq8(acc, u, dup_from_bits(c));
            j += 2;
        }
        if (j < cnt) {
            int s = __shfl_sync(0xFFFFFFFFu, idx, j);
            unsigned int c = __shfl_sync(0xFFFFFFFFu, scb, j);
            if (half == 0) {
                uint2 u = M8[(size_t)s * 16 + sub];
                addq8(acc, u, dup_from_bits(c));
            }
        }
    }

    // convert to fp32, combine the two halves (lanes 0-15 += lane+16)
    float fa[8];
#pragma unroll
    for (int k = 0; k < 4; k++) {
        float2 t = __half22float2(acc[k]);
        fa[2 * k] = t.x;
        fa[2 * k + 1] = t.y;
    }
#pragma unroll
    for (int k = 0; k < 8; k++)
        fa[k] += __shfl_down_sync(0xFFFFFFFFu, fa[k], 16);

    if (half == 0) {
        float di = g_dinv[warp];
        uint4 o;
        __half2* oh = (__half2*)&o;
#pragma unroll
        for (int i = 0; i < 4; i++)
            oh[i] = __floats2half2_rn(fa[2 * i] * di, fa[2 * i + 1] * di);
        H16[(size_t)warp * 16 + sub] = o;
    }
}

// ---------------- host launcher ---------------------------------------------
extern "C" void kernel_launch(void* const* d_in, const int* in_sizes, int n_in,
                              void* d_out, int out_size)
{
    const float* x   = (const float*)d_in[0];
    const int*   ei  = (const int*)d_in[1];
    const float* W0  = (const float*)d_in[2];
    const float* b0  = (const float*)d_in[3];
    const float* W1  = (const float*)d_in[4];
    const float* b1  = (const float*)d_in[5];
    const float* W2  = (const float*)d_in[6];
    const float* b2  = (const float*)d_in[7];
    const float* W3  = (const float*)d_in[8];
    const float* b3  = (const float*)d_in[9];
    const float* Wm1 = (const float*)d_in[10];
    const float* bm1 = (const float*)d_in[11];
    const float* Wm2 = (const float*)d_in[12];
    const float* bm2 = (const float*)d_in[13];
    float* out = (float*)d_out;

    const int n = in_sizes[0] / DIM;      // 100000
    const int e = in_sizes[1] / 2;        // 1600000
    const int* src = ei;
    const int* dst = ei + e;

    unsigned char* M8 = 0;
    __half* Sc = 0;
    __half* H16 = 0;
    __half* F16 = 0;
    __half* Wf = 0;
    cudaGetSymbolAddress((void**)&M8,  g_M8);
    cudaGetSymbolAddress((void**)&Sc,  g_sch);
    cudaGetSymbolAddress((void**)&H16, g_H16);
    cudaGetSymbolAddress((void**)&F16, g_F16);
    cudaGetSymbolAddress((void**)&Wf,  g_Wf);

    const int SM128 = 128 * PADB + 128 * PADB;   // 69632
    const int SM64  = 128 * PADB + 64 * PADB;    // 52224
    cudaFuncSetAttribute(k_gemm128, cudaFuncAttributeMaxDynamicSharedMemorySize, SM128);
    cudaFuncSetAttribute(k_gemm64s, cudaFuncAttributeMaxDynamicSharedMemorySize, SM64);

    // side stream + fork/join events (created once on the first — correctness —
    // call, outside graph capture; capture records only the event edges)
    static cudaStream_t s2 = 0;
    static cudaEvent_t evF = 0, evD = 0, evB = 0;
    if (!s2) {
        cudaStreamCreateWithFlags(&s2, cudaStreamNonBlocking);
        cudaEventCreateWithFlags(&evF, cudaEventDisableTiming);
        cudaEventCreateWithFlags(&evD, cudaEventDisableTiming);
        cudaEventCreateWithFlags(&evB, cudaEventDisableTiming);
    }

    const int nscanb = (n + SCHUNK - 1) / SCHUNK;
    const int gblocks = (n + 127) / 128;                 // 782
    const int gatherb = (n * 32 + 255) / 256;            // 12500

    // ---- fork: side branch gets weight convert (independent) ----
    cudaEventRecord(evF, 0);
    cudaStreamWaitEvent(s2, evF, 0);
    k_convW_all<<<(WTOT + 255) / 256, 256, 0, s2>>>(W0, W1, W2, W3, Wm1, Wm2);

    // ---- main branch: degrees -> dinv ----
    k_zero<<<(n + 255) / 256, 256>>>(n);
    k_count<<<(e + 255) / 256, 256>>>(dst, e);
    k_bsum<<<nscanb, SCHUNK>>>(n);           // also computes dinv
    cudaEventRecord(evD, 0);

    // side branch: layer-0 GEMM (needs Wf slot 0 + dinv + x only)
    cudaStreamWaitEvent(s2, evD, 0);
    k_gemm128<<<gblocks, 256, SM128, s2>>>(x, 0, 0, Wf + 0 * WSLOT, 0, M8, Sc, 0, n);
    cudaEventRecord(evB, s2);

    // main branch: CSR build (overlaps with gemm0 on s2)
    k_bscan<<<1, 128>>>(nscanb);
    k_offsets<<<nscanb, SCHUNK>>>(n);        // also preloads g_cur = g_off
    k_fill<<<(e + 255) / 256, 256>>>(src, dst, e);

    // ---- join: gather0 needs CSR (main) + messages (s2) ----
    cudaStreamWaitEvent(0, evB, 0);
    k_gather<<<gatherb, 256>>>((const uint2*)M8, Sc, (uint4*)H16, n);

    // ---- layers 1-3 ----
    k_gemm128<<<gblocks, 256, SM128>>>(0, H16, b0, Wf + 1 * WSLOT, 0, M8, Sc, 0, n);
    k_gather<<<gatherb, 256>>>((const uint2*)M8, Sc, (uint4*)H16, n);

    k_gemm128<<<gblocks, 256, SM128>>>(0, H16, b1, Wf + 2 * WSLOT, 0, M8, Sc, 0, n);
    k_gather<<<gatherb, 256>>>((const uint2*)M8, Sc, (uint4*)H16, n);

    k_gemm128<<<gblocks, 256, SM128>>>(0, H16, b2, Wf + 3 * WSLOT, 0, M8, Sc, 0, n);
    k_gather<<<gatherb, 256>>>((const uint2*)M8, Sc, (uint4*)H16, n);

    // ---- MLP1: F16 = half(relu(H16 + b3) @ Wm1 + bm1) ----
    k_gemm128<<<gblocks, 256, SM128>>>(0, H16, b3, Wf + 4 * WSLOT, bm1, 0, 0, F16, n);

    // ---- MLP2 + fused log_softmax -> out ----
    k_gemm64s<<<gblocks, 256, SM64>>>(F16, Wf + 5 * WSLOT, bm2, out, n);
}

// round 15
// speedup vs baseline: 1.9256x; 1.0547x over previous
#include <cuda_runtime.h>
#include <cuda_fp16.h>
#include <cstdint>
#include <stdint.h>
#include <math.h>

// Problem constants (fixed by the dataset)
#define N_NODES 100000
#define N_EDGES 1600000
#define DIM 128
#define ODIM 64
#define WSLOT 16384
#define WTOT (5 * WSLOT + ODIM * DIM)
#define PADB 272   // smem row stride in bytes, multiple of 16, conflict-free
#define SCHUNK 1024

// ---------------- scratch (static device globals; no allocation) -----------
__device__ unsigned char g_M8[(size_t)N_NODES * DIM]; // fp8-e4m3 messages
__device__ __half       g_sch[N_NODES];               // per-row dequant scale (fp16)
__device__ __half       g_H16[(size_t)N_NODES * DIM]; // fp16 aggregated features
__device__ int          g_deg[N_NODES];
__device__ int          g_cur[N_NODES];
__device__ int          g_off[N_NODES + 1];
__device__ int          g_csr[N_EDGES];
__device__ int          g_bsum[128];
__device__ float        g_dinv[N_NODES];
__device__ __half       g_Wf[WTOT];                   // fp16 transposed weights [N][K]

// ---------------- mma.sync fp16 helper (baseline PTX) ----------------------
__device__ __forceinline__ void mma_f16(float* c, const unsigned int* a,
                                        const unsigned int* b) {
    asm volatile(
        "mma.sync.aligned.m16n8k16.row.col.f32.f16.f16.f32 "
        "{%0,%1,%2,%3}, {%4,%5,%6,%7}, {%8,%9}, {%0,%1,%2,%3};"
        : "+f"(c[0]), "+f"(c[1]), "+f"(c[2]), "+f"(c[3])
        : "r"(a[0]), "r"(a[1]), "r"(a[2]), "r"(a[3]), "r"(b[0]), "r"(b[1]));
}

// fp8 pack/unpack (baseline PTX, sm_89+, valid at compute_100)
__device__ __forceinline__ unsigned short f32x2_to_e4m3x2(float hi, float lo) {
    unsigned short us;
    asm("cvt.rn.satfinite.e4m3x2.f32 %0, %1, %2;" : "=h"(us) : "f"(hi), "f"(lo));
    return us;   // byte0 = lo, byte1 = hi
}
__device__ __forceinline__ __half2 e4m3x2_to_h2(unsigned short w) {
    unsigned int r;
    asm("cvt.rn.f16x2.e4m3x2 %0, %1;" : "=r"(r) : "h"(w));
    return *(__half2*)&r;
}

// ---------------- setup kernels --------------------------------------------
__global__ void k_zero(int n) {
    int i = blockIdx.x * blockDim.x + threadIdx.x;
    if (i < n) g_deg[i] = 0;
}
__global__ void k_count(const int* __restrict__ dst, int e) {
    int i = blockIdx.x * blockDim.x + threadIdx.x;
    if (i < e) atomicAdd(&g_deg[dst[i]], 1);
}
__global__ void k_bsum(int n) {            // block sums + dinv (deg final here)
    __shared__ int sh[SCHUNK];
    int i = blockIdx.x * SCHUNK + threadIdx.x;
    int d = (i < n) ? g_deg[i] : 0;
    if (i < n) g_dinv[i] = rsqrtf((float)(d + 1));
    sh[threadIdx.x] = d;
    __syncthreads();
    for (int off = SCHUNK / 2; off > 0; off >>= 1) {
        if (threadIdx.x < off) sh[threadIdx.x] += sh[threadIdx.x + off];
        __syncthreads();
    }
    if (threadIdx.x == 0) g_bsum[blockIdx.x] = sh[0];
}
__global__ void k_bscan(int nb) {
    __shared__ int sh[128];
    int v = (threadIdx.x < nb) ? g_bsum[threadIdx.x] : 0;
    sh[threadIdx.x] = v;
    __syncthreads();
    for (int off = 1; off < 128; off <<= 1) {
        int t = (threadIdx.x >= off) ? sh[threadIdx.x - off] : 0;
        __syncthreads();
        sh[threadIdx.x] += t;
        __syncthreads();
    }
    if (threadIdx.x < nb) g_bsum[threadIdx.x] = sh[threadIdx.x] - v;
}
__global__ void k_offsets(int n) {
    __shared__ int sh[SCHUNK];
    int i = blockIdx.x * SCHUNK + threadIdx.x;
    int v = (i < n) ? g_deg[i] : 0;
    sh[threadIdx.x] = v;
    __syncthreads();
    for (int off = 1; off < SCHUNK; off <<= 1) {
        int t = (threadIdx.x >= off) ? sh[threadIdx.x - off] : 0;
        __syncthreads();
        sh[threadIdx.x] += t;
        __syncthreads();
    }
    int excl = g_bsum[blockIdx.x] + sh[threadIdx.x] - v;
    if (i < n) { g_off[i] = excl; g_cur[i] = excl; }   // cur preloaded as cursor
    if (i == n - 1) g_off[n] = excl + v;
}
__global__ void k_fill(const int* __restrict__ src, const int* __restrict__ dst, int e) {
    int i = blockIdx.x * blockDim.x + threadIdx.x;
    if (i < e) {
        int pos = atomicAdd(&g_cur[dst[i]], 1);
        g_csr[pos] = src[i];
    }
}
__global__ void k_convW_all(const float* __restrict__ W0, const float* __restrict__ W1,
                            const float* __restrict__ W2, const float* __restrict__ W3,
                            const float* __restrict__ Wm1, const float* __restrict__ Wm2) {
    int i = blockIdx.x * blockDim.x + threadIdx.x;
    if (i >= WTOT) return;
    int slot = i >> 14;
    int j = i & 16383;
    const float* W;
    int N;
    switch (slot) {
        case 0:  W = W0;  N = 128; break;
        case 1:  W = W1;  N = 128; break;
        case 2:  W = W2;  N = 128; break;
        case 3:  W = W3;  N = 128; break;
        case 4:  W = Wm1; N = 128; break;
        default: W = Wm2; N = 64;  break;
    }
    const int K = 128;
    int nrow = j / K;
    int k = j % K;
    g_Wf[i] = __float2half_rn(W[k * N + nrow]);
}

// ---------------- GCN-layer GEMM: fp8 message quant epilogue ----------------
// acc = act(A) @ W; act = relu(a+abias) if abias (A16 or A32 input).
// Epilogue: per-row absmax M; C8 = e4m3(acc * 240/M); Csc = fp16(M*dinv/240).
__global__ void __launch_bounds__(256, 2)
k_gemm128(const float* __restrict__ A32, const __half* __restrict__ A16,
          const float* __restrict__ abias, const __half* __restrict__ Wf,
          unsigned char* __restrict__ C8, __half* __restrict__ Csc, int n)
{
    extern __shared__ __align__(16) char smem[];
    const unsigned int A_OF = 0;
    const unsigned int B_OF = 128 * PADB;
    const int tid  = threadIdx.x;
    const int wid  = tid >> 5;
    const int lane = tid & 31;
    const int wr   = wid >> 1;
    const int wc   = wid & 1;
    const int row0 = blockIdx.x * 128;

    // ---- A tile -> fp16 smem, fused relu(+abias)
    for (int i = tid; i < 128 * 16; i += 256) {
        int row = i >> 4;
        int unit = i & 15;
        int grow = row0 + row;
        uint4 u = make_uint4(0, 0, 0, 0);
        __half2* hp = (__half2*)&u;
        if (grow < n) {
            if (A16) {
                u = *(const uint4*)(A16 + (size_t)grow * 128 + unit * 8);
            } else {
                const float4* p = (const float4*)(A32 + (size_t)grow * 128 + unit * 8);
                float4 a0 = p[0], a1 = p[1];
                hp[0] = __floats2half2_rn(a0.x, a0.y);
                hp[1] = __floats2half2_rn(a0.z, a0.w);
                hp[2] = __floats2half2_rn(a1.x, a1.y);
                hp[3] = __floats2half2_rn(a1.z, a1.w);
            }
        }
        if (abias) {
            const float4* b = (const float4*)(abias + unit * 8);
            float4 b0 = b[0], b1 = b[1];
            float bb[8];
            bb[0] = b0.x; bb[1] = b0.y; bb[2] = b0.z; bb[3] = b0.w;
            bb[4] = b1.x; bb[5] = b1.y; bb[6] = b1.z; bb[7] = b1.w;
#pragma unroll
            for (int j = 0; j < 4; j++) {
                float2 f = __half22float2(hp[j]);
                f.x = fmaxf(f.x + bb[2 * j], 0.f);
                f.y = fmaxf(f.y + bb[2 * j + 1], 0.f);
                hp[j] = __floats2half2_rn(f.x, f.y);
            }
        }
        *(uint4*)(smem + A_OF + (unsigned int)row * PADB + (unsigned int)unit * 16) = u;
    }
    // ---- W tile (128 rows)
    for (int i = tid; i < 128 * 16; i += 256) {
        int row = i >> 4;
        int unit = i & 15;
        *(uint4*)(smem + B_OF + (unsigned int)row * PADB + (unsigned int)unit * 16) =
            ((const uint4*)Wf)[row * 16 + unit];
    }
    __syncthreads();

    const int g  = lane >> 2;
    const int tg = lane & 3;
    float acc[2][8][4];
#pragma unroll
    for (int mt = 0; mt < 2; mt++)
#pragma unroll
        for (int nt = 0; nt < 8; nt++)
#pragma unroll
            for (int j = 0; j < 4; j++) acc[mt][nt][j] = 0.f;

#pragma unroll
    for (int ks = 0; ks < 8; ks++) {
        const unsigned int kb = (unsigned int)(ks * 16 + tg * 2) * 2;
        unsigned int a[2][4];
#pragma unroll
        for (int mt = 0; mt < 2; mt++) {
            unsigned int ro = A_OF + (unsigned int)(wr * 32 + mt * 16 + g) * PADB + kb;
            a[mt][0] = *(const unsigned int*)(smem + ro);
            a[mt][1] = *(const unsigned int*)(smem + ro + 8 * PADB);
            a[mt][2] = *(const unsigned int*)(smem + ro + 16);
            a[mt][3] = *(const unsigned int*)(smem + ro + 8 * PADB + 16);
        }
#pragma unroll
        for (int nt = 0; nt < 8; nt++) {
            unsigned int no = B_OF + (unsigned int)(wc * 64 + nt * 8 + g) * PADB + kb;
            unsigned int b[2];
            b[0] = *(const unsigned int*)(smem + no);
            b[1] = *(const unsigned int*)(smem + no + 16);
#pragma unroll
            for (int mt = 0; mt < 2; mt++)
                mma_f16(acc[mt][nt], a[mt], b);
        }
    }

    // ---- fp8 quant epilogue
    __syncthreads();
    float* rmax = (float*)smem;
    if (tid < 128) rmax[tid] = 0.f;
    __syncthreads();
#pragma unroll
    for (int mt = 0; mt < 2; mt++) {
        int lr = wr * 32 + mt * 16 + g;
        float m0 = 0.f, m1 = 0.f;
#pragma unroll
        for (int nt = 0; nt < 8; nt++) {
            m0 = fmaxf(m0, fmaxf(fabsf(acc[mt][nt][0]), fabsf(acc[mt][nt][1])));
            m1 = fmaxf(m1, fmaxf(fabsf(acc[mt][nt][2]), fabsf(acc[mt][nt][3])));
        }
        atomicMax((int*)&rmax[lr], __float_as_int(m0));
        atomicMax((int*)&rmax[lr + 8], __float_as_int(m1));
    }
    __syncthreads();
#pragma unroll
    for (int mt = 0; mt < 2; mt++) {
        int lr = wr * 32 + mt * 16 + g;
        int grow = row0 + lr;
        float M0 = rmax[lr], M1 = rmax[lr + 8];
        float q0 = (M0 > 0.f) ? 240.f / M0 : 0.f;
        float q1 = (M1 > 0.f) ? 240.f / M1 : 0.f;
        if (wc == 0 && tg == 0) {
            if (grow < n)
                Csc[grow] = __float2half_rn(M0 * g_dinv[grow] * (1.f / 240.f));
            if (grow + 8 < n)
                Csc[grow + 8] = __float2half_rn(M1 * g_dinv[grow + 8] * (1.f / 240.f));
        }
#pragma unroll
        for (int nt = 0; nt < 8; nt++) {
            int col = wc * 64 + nt * 8 + tg * 2;
            if (grow < n)
                *(unsigned short*)(C8 + (size_t)grow * 128 + col) =
                    f32x2_to_e4m3x2(acc[mt][nt][1] * q0, acc[mt][nt][0] * q0);
            if (grow + 8 < n)
                *(unsigned short*)(C8 + (size_t)(grow + 8) * 128 + col) =
                    f32x2_to_e4m3x2(acc[mt][nt][3] * q1, acc[mt][nt][2] * q1);
        }
    }
}

// ---------------- fused MLP: relu(H+b3)@Wm1+bm1 -> @Wm2+bm2 -> log_softmax --
__global__ void __launch_bounds__(256, 2)
k_mlp(const __half* __restrict__ A16, const float* __restrict__ b3,
      const __half* __restrict__ Wm1f, const float* __restrict__ bm1,
      const __half* __restrict__ Wm2f, const float* __restrict__ bm2,
      float* __restrict__ osm, int n)
{
    extern __shared__ __align__(16) char smem[];
    const unsigned int A_OF = 0;
    const unsigned int B_OF = 128 * PADB;
    const int tid  = threadIdx.x;
    const int wid  = tid >> 5;
    const int lane = tid & 31;
    const int wr   = wid >> 1;
    const int wc   = wid & 1;
    const int row0 = blockIdx.x * 128;
    const int g  = lane >> 2;
    const int tg = lane & 3;

    // ---- A = relu(H16 + b3) tile; B = Wm1 tile
    for (int i = tid; i < 128 * 16; i += 256) {
        int row = i >> 4;
        int unit = i & 15;
        int grow = row0 + row;
        uint4 u = make_uint4(0, 0, 0, 0);
        __half2* hp = (__half2*)&u;
        if (grow < n) u = *(const uint4*)(A16 + (size_t)grow * 128 + unit * 8);
        const float4* b = (const float4*)(b3 + unit * 8);
        float4 b0 = b[0], b1 = b[1];
        float bb[8];
        bb[0] = b0.x; bb[1] = b0.y; bb[2] = b0.z; bb[3] = b0.w;
        bb[4] = b1.x; bb[5] = b1.y; bb[6] = b1.z; bb[7] = b1.w;
#pragma unroll
        for (int j = 0; j < 4; j++) {
            float2 f = __half22float2(hp[j]);
            f.x = fmaxf(f.x + bb[2 * j], 0.f);
            f.y = fmaxf(f.y + bb[2 * j + 1], 0.f);
            hp[j] = __floats2half2_rn(f.x, f.y);
        }
        *(uint4*)(smem + A_OF + (unsigned int)row * PADB + (unsigned int)unit * 16) = u;
    }
    for (int i = tid; i < 128 * 16; i += 256) {
        int row = i >> 4;
        int unit = i & 15;
        *(uint4*)(smem + B_OF + (unsigned int)row * PADB + (unsigned int)unit * 16) =
            ((const uint4*)Wm1f)[row * 16 + unit];
    }
    __syncthreads();

    // ---- MMA 1: T = A @ Wm1 (128 cols)
    float acc[2][8][4];
#pragma unroll
    for (int mt = 0; mt < 2; mt++)
#pragma unroll
        for (int nt = 0; nt < 8; nt++)
#pragma unroll
            for (int j = 0; j < 4; j++) acc[mt][nt][j] = 0.f;

#pragma unroll
    for (int ks = 0; ks < 8; ks++) {
        const unsigned int kb = (unsigned int)(ks * 16 + tg * 2) * 2;
        unsigned int a[2][4];
#pragma unroll
        for (int mt = 0; mt < 2; mt++) {
            unsigned int ro = A_OF + (unsigned int)(wr * 32 + mt * 16 + g) * PADB + kb;
            a[mt][0] = *(const unsigned int*)(smem + ro);
            a[mt][1] = *(const unsigned int*)(smem + ro + 8 * PADB);
            a[mt][2] = *(const unsigned int*)(smem + ro + 16);
            a[mt][3] = *(const unsigned int*)(smem + ro + 8 * PADB + 16);
        }
#pragma unroll
        for (int nt = 0; nt < 8; nt++) {
            unsigned int no = B_OF + (unsigned int)(wc * 64 + nt * 8 + g) * PADB + kb;
            unsigned int b[2];
            b[0] = *(const unsigned int*)(smem + no);
            b[1] = *(const unsigned int*)(smem + no + 16);
#pragma unroll
            for (int mt = 0; mt < 2; mt++)
                mma_f16(acc[mt][nt], a[mt], b);
        }
    }

    __syncthreads();   // all MMA1 reads of A and B complete

    // ---- write T (=acc+bm1, fp16) into A area; load Wm2 into B area
#pragma unroll
    for (int mt = 0; mt < 2; mt++) {
        int lr = wr * 32 + mt * 16 + g;
#pragma unroll
        for (int nt = 0; nt < 8; nt++) {
            int col = wc * 64 + nt * 8 + tg * 2;
            float b0 = bm1[col], b1 = bm1[col + 1];
            *(__half2*)(smem + A_OF + (unsigned int)lr * PADB + col * 2) =
                __floats2half2_rn(acc[0 * 0 + mt][nt][0] + b0, acc[mt][nt][1] + b1);
            *(__half2*)(smem + A_OF + (unsigned int)(lr + 8) * PADB + col * 2) =
                __floats2half2_rn(acc[mt][nt][2] + b0, acc[mt][nt][3] + b1);
        }
    }
    for (int i = tid; i < 64 * 16; i += 256) {
        int row = i >> 4;
        int unit = i & 15;
        *(uint4*)(smem + B_OF + (unsigned int)row * PADB + (unsigned int)unit * 16) =
            ((const uint4*)Wm2f)[row * 16 + unit];
    }
    __syncthreads();

    // ---- MMA 2: C = T @ Wm2 (64 cols)
#pragma unroll
    for (int mt = 0; mt < 2; mt++)
#pragma unroll
        for (int nt = 0; nt < 4; nt++)
#pragma unroll
            for (int j = 0; j < 4; j++) acc[mt][nt][j] = 0.f;

#pragma unroll
    for (int ks = 0; ks < 8; ks++) {
        const unsigned int kb = (unsigned int)(ks * 16 + tg * 2) * 2;
        unsigned int a[2][4];
#pragma unroll
        for (int mt = 0; mt < 2; mt++) {
            unsigned int ro = A_OF + (unsigned int)(wr * 32 + mt * 16 + g) * PADB + kb;
            a[mt][0] = *(const unsigned int*)(smem + ro);
            a[mt][1] = *(const unsigned int*)(smem + ro + 8 * PADB);
            a[mt][2] = *(const unsigned int*)(smem + ro + 16);
            a[mt][3] = *(const unsigned int*)(smem + ro + 8 * PADB + 16);
        }
#pragma unroll
        for (int nt = 0; nt < 4; nt++) {
            unsigned int no = B_OF + (unsigned int)(wc * 32 + nt * 8 + g) * PADB + kb;
            unsigned int b[2];
            b[0] = *(const unsigned int*)(smem + no);
            b[1] = *(const unsigned int*)(smem + no + 16);
#pragma unroll
            for (int mt = 0; mt < 2; mt++)
                mma_f16(acc[mt][nt], a[mt], b);
        }
    }

    __syncthreads();   // all MMA2 reads of T complete

    // ---- fused log_softmax (sx reuses A area: 128 rows x 68 floats)
    float* sx = (float*)smem;
#pragma unroll
    for (int mt = 0; mt < 2; mt++) {
        int lr = wr * 32 + mt * 16 + g;
#pragma unroll
        for (int nt = 0; nt < 4; nt++) {
            int col = wc * 32 + nt * 8 + tg * 2;
            float b0 = bm2[col], b1 = bm2[col + 1];
            *(float2*)(sx + lr * 68 + col) =
                make_float2(acc[mt][nt][0] + b0, acc[mt][nt][1] + b1);
            *(float2*)(sx + (lr + 8) * 68 + col) =
                make_float2(acc[mt][nt][2] + b0, acc[mt][nt][3] + b1);
        }
    }
    __syncthreads();
    for (int r = wid * 16; r < wid * 16 + 16; r++) {
        int grow = row0 + r;
        if (grow >= n) break;
        float v0 = sx[r * 68 + lane];
        float v1 = sx[r * 68 + lane + 32];
        float m = fmaxf(v0, v1);
#pragma unroll
        for (int o = 16; o > 0; o >>= 1)
            m = fmaxf(m, __shfl_xor_sync(0xFFFFFFFFu, m, o));
        float s = expf(v0 - m) + expf(v1 - m);
#pragma unroll
        for (int o = 16; o > 0; o >>= 1)
            s += __shfl_xor_sync(0xFFFFFFFFu, s, o);
        float lg = m + logf(s);
        osm[(size_t)grow * 64 + lane]      = v0 - lg;
        osm[(size_t)grow * 64 + lane + 32] = v1 - lg;
    }
}

// ---------------- CSR pull-gather (fp8 rows, packed idx+scale shfl) --------
// H16[d] = half( dinv[d] * sum_{s in N(d) U {d}} sc[s] * M8[s] )
// Packed lane word: bits[0:17) = idx, bits[17:32) = fp16 scale bits >> 1.
__device__ __forceinline__ void addq8(__half2* a, uint2 u, __half2 s) {
    a[0] = __hfma2(e4m3x2_to_h2((unsigned short)(u.x)), s, a[0]);
    a[1] = __hfma2(e4m3x2_to_h2((unsigned short)(u.x >> 16)), s, a[1]);
    a[2] = __hfma2(e4m3x2_to_h2((unsigned short)(u.y)), s, a[2]);
    a[3] = __hfma2(e4m3x2_to_h2((unsigned short)(u.y >> 16)), s, a[3]);
}
__device__ __forceinline__ __half2 sc_of(unsigned int c) {
    return __half2half2(__ushort_as_half((unsigned short)((c >> 16) & 0xFFFEu)));
}
__device__ __forceinline__ int idx_of(unsigned int c) { return (int)(c & 0x1FFFFu); }

__launch_bounds__(256)
__global__ void k_gather(const uint2* __restrict__ M8,   // row = 16 uint2
                         const __half* __restrict__ sch,
                         uint4* __restrict__ H16, int n)  // row = 16 uint4
{
    int warp = (blockIdx.x * blockDim.x + threadIdx.x) >> 5;
    int lane = threadIdx.x & 31;
    if (warp >= n) return;
    int half = lane >> 4;
    int sub  = lane & 15;
    int beg = g_off[warp];
    int total = g_off[warp + 1] - beg + 1;   // +1 self loop (virtual idx 0)

    __half2 acc[4];
#pragma unroll
    for (int k = 0; k < 4; k++) acc[k] = __half2half2(__ushort_as_half(0));

    for (int base = 0; base < total; base += 32) {
        int cnt = total - base;
        if (cnt > 32) cnt = 32;
        int vj = base + lane;
        unsigned int pk = 0;
        if (lane < cnt) {
            int idx = (vj == 0) ? warp : g_csr[beg + vj - 1];
            unsigned int scb = (unsigned int)__half_as_ushort(sch[idx]);
            pk = ((scb & 0xFFFEu) << 16) | (unsigned int)idx;
        }
        int j = 0;
        for (; j + 8 <= cnt; j += 8) {
            unsigned int c0 = __shfl_sync(0xFFFFFFFFu, pk, j + half);
            unsigned int c1 = __shfl_sync(0xFFFFFFFFu, pk, j + 2 + half);
            unsigned int c2 = __shfl_sync(0xFFFFFFFFu, pk, j + 4 + half);
            unsigned int c3 = __shfl_sync(0xFFFFFFFFu, pk, j + 6 + half);
            uint2 u0 = M8[(size_t)idx_of(c0) * 16 + sub];
            uint2 u1 = M8[(size_t)idx_of(c1) * 16 + sub];
            uint2 u2 = M8[(size_t)idx_of(c2) * 16 + sub];
            uint2 u3 = M8[(size_t)idx_of(c3) * 16 + sub];
            addq8(acc, u0, sc_of(c0));
            addq8(acc, u1, sc_of(c1));
            addq8(acc, u2, sc_of(c2));
            addq8(acc, u3, sc_of(c3));
        }
        if (j + 4 <= cnt) {
            unsigned int c0 = __shfl_sync(0xFFFFFFFFu, pk, j + half);
            unsigned int c1 = __shfl_sync(0xFFFFFFFFu, pk, j + 2 + half);
            uint2 u0 = M8[(size_t)idx_of(c0) * 16 + sub];
            uint2 u1 = M8[(size_t)idx_of(c1) * 16 + sub];
            addq8(acc, u0, sc_of(c0));
            addq8(acc, u1, sc_of(c1));
            j += 4;
        }
        if (j + 2 <= cnt) {
            unsigned int c = __shfl_sync(0xFFFFFFFFu, pk, j + half);
            uint2 u = M8[(size_t)idx_of(c) * 16 + sub];
            addq8(acc, u, sc_of(c));
            j += 2;
        }
        if (j < cnt) {
            unsigned int c = __shfl_sync(0xFFFFFFFFu, pk, j);
            if (half == 0) {
                uint2 u = M8[(size_t)idx_of(c) * 16 + sub];
                addq8(acc, u, sc_of(c));
            }
        }
    }

    float fa[8];
#pragma unroll
    for (int k = 0; k < 4; k++) {
        float2 t = __half22float2(acc[k]);
        fa[2 * k] = t.x;
        fa[2 * k + 1] = t.y;
    }
#pragma unroll
    for (int k = 0; k < 8; k++)
        fa[k] += __shfl_down_sync(0xFFFFFFFFu, fa[k], 16);

    if (half == 0) {
        float di = g_dinv[warp];
        uint4 o;
        __half2* oh = (__half2*)&o;
#pragma unroll
        for (int i = 0; i < 4; i++)
            oh[i] = __floats2half2_rn(fa[2 * i] * di, fa[2 * i + 1] * di);
        H16[(size_t)warp * 16 + sub] = o;
    }
}

// ---------------- host launcher ---------------------------------------------
extern "C" void kernel_launch(void* const* d_in, const int* in_sizes, int n_in,
                              void* d_out, int out_size)
{
    const float* x   = (const float*)d_in[0];
    const int*   ei  = (const int*)d_in[1];
    const float* W0  = (const float*)d_in[2];
    const float* b0  = (const float*)d_in[3];
    const float* W1  = (const float*)d_in[4];
    const float* b1  = (const float*)d_in[5];
    const float* W2  = (const float*)d_in[6];
    const float* b2  = (const float*)d_in[7];
    const float* W3  = (const float*)d_in[8];
    const float* b3  = (const float*)d_in[9];
    const float* Wm1 = (const float*)d_in[10];
    const float* bm1 = (const float*)d_in[11];
    const float* Wm2 = (const float*)d_in[12];
    const float* bm2 = (const float*)d_in[13];
    float* out = (float*)d_out;

    const int n = in_sizes[0] / DIM;      // 100000
    const int e = in_sizes[1] / 2;        // 1600000
    const int* src = ei;
    const int* dst = ei + e;

    unsigned char* M8 = 0;
    __half* Sc = 0;
    __half* H16 = 0;
    __half* Wf = 0;
    cudaGetSymbolAddress((void**)&M8,  g_M8);
    cudaGetSymbolAddress((void**)&Sc,  g_sch);
    cudaGetSymbolAddress((void**)&H16, g_H16);
    cudaGetSymbolAddress((void**)&Wf,  g_Wf);

    const int SM128 = 128 * PADB + 128 * PADB;   // 69632
    cudaFuncSetAttribute(k_gemm128, cudaFuncAttributeMaxDynamicSharedMemorySize, SM128);
    cudaFuncSetAttribute(k_mlp,     cudaFuncAttributeMaxDynamicSharedMemorySize, SM128);

    // side stream + fork/join events (created once on the first — correctness —
    // call, outside graph capture; capture records only the event edges)
    static cudaStream_t s2 = 0;
    static cudaEvent_t evF = 0, evD = 0, evB = 0;
    if (!s2) {
        cudaStreamCreateWithFlags(&s2, cudaStreamNonBlocking);
        cudaEventCreateWithFlags(&evF, cudaEventDisableTiming);
        cudaEventCreateWithFlags(&evD, cudaEventDisableTiming);
        cudaEventCreateWithFlags(&evB, cudaEventDisableTiming);
    }

    const int nscanb = (n + SCHUNK - 1) / SCHUNK;
    const int gblocks = (n + 127) / 128;                 // 782
    const int gatherb = (n * 32 + 255) / 256;            // 12500

    // ---- fork: side branch gets weight convert (independent) ----
    cudaEventRecord(evF, 0);
    cudaStreamWaitEvent(s2, evF, 0);
    k_convW_all<<<(WTOT + 255) / 256, 256, 0, s2>>>(W0, W1, W2, W3, Wm1, Wm2);

    // ---- main branch: degrees -> dinv ----
    k_zero<<<(n + 255) / 256, 256>>>(n);
    k_count<<<(e + 255) / 256, 256>>>(dst, e);
    k_bsum<<<nscanb, SCHUNK>>>(n);           // also computes dinv
    cudaEventRecord(evD, 0);

    // side branch: layer-0 GEMM (needs Wf slot 0 + dinv + x only)
    cudaStreamWaitEvent(s2, evD, 0);
    k_gemm128<<<gblocks, 256, SM128, s2>>>(x, 0, 0, Wf + 0 * WSLOT, M8, Sc, n);
    cudaEventRecord(evB, s2);

    // main branch: CSR build (overlaps with gemm0 on s2)
    k_bscan<<<1, 128>>>(nscanb);
    k_offsets<<<nscanb, SCHUNK>>>(n);        // also preloads g_cur = g_off
    k_fill<<<(e + 255) / 256, 256>>>(src, dst, e);

    // ---- join: gather0 needs CSR (main) + messages (s2) ----
    cudaStreamWaitEvent(0, evB, 0);
    k_gather<<<gatherb, 256>>>((const uint2*)M8, Sc, (uint4*)H16, n);

    // ---- layers 1-3 ----
    k_gemm128<<<gblocks, 256, SM128>>>(0, H16, b0, Wf + 1 * WSLOT, M8, Sc, n);
    k_gather<<<gatherb, 256>>>((const uint2*)M8, Sc, (uint4*)H16, n);

    k_gemm128<<<gblocks, 256, SM128>>>(0, H16, b1, Wf + 2 * WSLOT, M8, Sc, n);
    k_gather<<<gatherb, 256>>>((const uint2*)M8, Sc, (uint4*)H16, n);

    k_gemm128<<<gblocks, 256, SM128>>>(0, H16, b2, Wf + 3 * WSLOT, M8, Sc, n);
    k_gather<<<gatherb, 256>>>((const uint2*)M8, Sc, (uint4*)H16, n);

    // ---- fused MLP1 + MLP2 + log_softmax -> out ----
    k_mlp<<<gblocks, 256, SM128>>>(H16, b3, Wf + 4 * WSLOT, bm1,
                                   Wf + 5 * WSLOT, bm2, out, n);
}

// round 16
// speedup vs baseline: 2.0788x; 1.0795x over previous
#include <cuda_runtime.h>
#include <cuda_fp16.h>
#include <cstdint>
#include <stdint.h>
#include <math.h>

// Problem constants (fixed by the dataset)
#define N_NODES 100000
#define N_EDGES 1600000
#define DIM 128
#define ODIM 64
#define WSLOT 16384
#define WTOT (5 * WSLOT + ODIM * DIM)
#define PADB 272   // smem row stride in bytes, multiple of 16, conflict-free
#define SCHUNK 1024

// ---------------- scratch (static device globals; no allocation) -----------
__device__ unsigned char g_M8[(size_t)N_NODES * DIM]; // fp8-e4m3 messages (pre-scaled by dinv_src)
__device__ __half       g_H16[(size_t)N_NODES * DIM]; // fp16 aggregated features
__device__ int          g_deg[N_NODES];
__device__ int          g_cur[N_NODES];
__device__ int          g_off[N_NODES + 1];
__device__ int          g_csr[N_EDGES];
__device__ int          g_bsum[128];
__device__ float        g_dinv[N_NODES];
__device__ __half       g_Wf[WTOT];                   // fp16 transposed weights [N][K]

// ---------------- mma.sync fp16 helper (baseline PTX) ----------------------
__device__ __forceinline__ void mma_f16(float* c, const unsigned int* a,
                                        const unsigned int* b) {
    asm volatile(
        "mma.sync.aligned.m16n8k16.row.col.f32.f16.f16.f32 "
        "{%0,%1,%2,%3}, {%4,%5,%6,%7}, {%8,%9}, {%0,%1,%2,%3};"
        : "+f"(c[0]), "+f"(c[1]), "+f"(c[2]), "+f"(c[3])
        : "r"(a[0]), "r"(a[1]), "r"(a[2]), "r"(a[3]), "r"(b[0]), "r"(b[1]));
}

// fp8 pack/unpack (baseline PTX, sm_89+, valid at compute_100)
__device__ __forceinline__ unsigned short f32x2_to_e4m3x2(float hi, float lo) {
    unsigned short us;
    asm("cvt.rn.satfinite.e4m3x2.f32 %0, %1, %2;" : "=h"(us) : "f"(hi), "f"(lo));
    return us;   // byte0 = lo, byte1 = hi
}
__device__ __forceinline__ __half2 e4m3x2_to_h2(unsigned short w) {
    unsigned int r;
    asm("cvt.rn.f16x2.e4m3x2 %0, %1;" : "=r"(r) : "h"(w));
    return *(__half2*)&r;
}

// ---------------- setup kernels --------------------------------------------
__global__ void k_count(const int* __restrict__ dst, int e) {
    int i = blockIdx.x * blockDim.x + threadIdx.x;
    if (i < e) atomicAdd(&g_deg[dst[i]], 1);
}
__global__ void k_bsum(int n) {            // block sums + dinv (deg final here)
    __shared__ int sh[SCHUNK];
    int i = blockIdx.x * SCHUNK + threadIdx.x;
    int d = (i < n) ? g_deg[i] : 0;
    if (i < n) g_dinv[i] = rsqrtf((float)(d + 1));
    sh[threadIdx.x] = d;
    __syncthreads();
    for (int off = SCHUNK / 2; off > 0; off >>= 1) {
        if (threadIdx.x < off) sh[threadIdx.x] += sh[threadIdx.x + off];
        __syncthreads();
    }
    if (threadIdx.x == 0) g_bsum[blockIdx.x] = sh[0];
}
__global__ void k_bscan(int nb) {
    __shared__ int sh[128];
    int v = (threadIdx.x < nb) ? g_bsum[threadIdx.x] : 0;
    sh[threadIdx.x] = v;
    __syncthreads();
    for (int off = 1; off < 128; off <<= 1) {
        int t = (threadIdx.x >= off) ? sh[threadIdx.x - off] : 0;
        __syncthreads();
        sh[threadIdx.x] += t;
        __syncthreads();
    }
    if (threadIdx.x < nb) g_bsum[threadIdx.x] = sh[threadIdx.x] - v;
}
__global__ void k_offsets(int n) {
    __shared__ int sh[SCHUNK];
    int i = blockIdx.x * SCHUNK + threadIdx.x;
    int v = (i < n) ? g_deg[i] : 0;
    sh[threadIdx.x] = v;
    __syncthreads();
    for (int off = 1; off < SCHUNK; off <<= 1) {
        int t = (threadIdx.x >= off) ? sh[threadIdx.x - off] : 0;
        __syncthreads();
        sh[threadIdx.x] += t;
        __syncthreads();
    }
    int excl = g_bsum[blockIdx.x] + sh[threadIdx.x] - v;
    if (i < n) { g_off[i] = excl; g_cur[i] = excl; }   // cur preloaded as cursor
    if (i == n - 1) g_off[n] = excl + v;
}
__global__ void k_fill(const int* __restrict__ src, const int* __restrict__ dst, int e) {
    int i = blockIdx.x * blockDim.x + threadIdx.x;
    if (i < e) {
        int pos = atomicAdd(&g_cur[dst[i]], 1);
        g_csr[pos] = src[i];
    }
}
__global__ void k_convW_all(const float* __restrict__ W0, const float* __restrict__ W1,
                            const float* __restrict__ W2, const float* __restrict__ W3,
                            const float* __restrict__ Wm1, const float* __restrict__ Wm2) {
    int i = blockIdx.x * blockDim.x + threadIdx.x;
    if (i >= WTOT) return;
    int slot = i >> 14;
    int j = i & 16383;
    const float* W;
    int N;
    switch (slot) {
        case 0:  W = W0;  N = 128; break;
        case 1:  W = W1;  N = 128; break;
        case 2:  W = W2;  N = 128; break;
        case 3:  W = W3;  N = 128; break;
        case 4:  W = Wm1; N = 128; break;
        default: W = Wm2; N = 64;  break;
    }
    const int K = 128;
    int nrow = j / K;
    int k = j % K;
    g_Wf[i] = __float2half_rn(W[k * N + nrow]);
}

// ---------------- GCN-layer GEMM: scale-free fp8 message epilogue ----------
// acc = act(A) @ W; act = relu(a+abias) if abias (A16 or A32 input).
// Epilogue: C8[row] = e4m3(acc * dinv[row])   (single rounding, no absmax)
__global__ void __launch_bounds__(256, 2)
k_gemm128(const float* __restrict__ A32, const __half* __restrict__ A16,
          const float* __restrict__ abias, const __half* __restrict__ Wf,
          unsigned char* __restrict__ C8, int n)
{
    extern __shared__ __align__(16) char smem[];
    const unsigned int A_OF = 0;
    const unsigned int B_OF = 128 * PADB;
    const int tid  = threadIdx.x;
    const int wid  = tid >> 5;
    const int lane = tid & 31;
    const int wr   = wid >> 1;
    const int wc   = wid & 1;
    const int row0 = blockIdx.x * 128;

    // ---- A tile -> fp16 smem, fused relu(+abias)
    for (int i = tid; i < 128 * 16; i += 256) {
        int row = i >> 4;
        int unit = i & 15;
        int grow = row0 + row;
        uint4 u = make_uint4(0, 0, 0, 0);
        __half2* hp = (__half2*)&u;
        if (grow < n) {
            if (A16) {
                u = *(const uint4*)(A16 + (size_t)grow * 128 + unit * 8);
            } else {
                const float4* p = (const float4*)(A32 + (size_t)grow * 128 + unit * 8);
                float4 a0 = p[0], a1 = p[1];
                hp[0] = __floats2half2_rn(a0.x, a0.y);
                hp[1] = __floats2half2_rn(a0.z, a0.w);
                hp[2] = __floats2half2_rn(a1.x, a1.y);
                hp[3] = __floats2half2_rn(a1.z, a1.w);
            }
        }
        if (abias) {
            const float4* b = (const float4*)(abias + unit * 8);
            float4 b0 = b[0], b1 = b[1];
            float bb[8];
            bb[0] = b0.x; bb[1] = b0.y; bb[2] = b0.z; bb[3] = b0.w;
            bb[4] = b1.x; bb[5] = b1.y; bb[6] = b1.z; bb[7] = b1.w;
#pragma unroll
            for (int j = 0; j < 4; j++) {
                float2 f = __half22float2(hp[j]);
                f.x = fmaxf(f.x + bb[2 * j], 0.f);
                f.y = fmaxf(f.y + bb[2 * j + 1], 0.f);
                hp[j] = __floats2half2_rn(f.x, f.y);
            }
        }
        *(uint4*)(smem + A_OF + (unsigned int)row * PADB + (unsigned int)unit * 16) = u;
    }
    // ---- W tile (128 rows)
    for (int i = tid; i < 128 * 16; i += 256) {
        int row = i >> 4;
        int unit = i & 15;
        *(uint4*)(smem + B_OF + (unsigned int)row * PADB + (unsigned int)unit * 16) =
            ((const uint4*)Wf)[row * 16 + unit];
    }
    __syncthreads();

    const int g  = lane >> 2;
    const int tg = lane & 3;
    float acc[2][8][4];
#pragma unroll
    for (int mt = 0; mt < 2; mt++)
#pragma unroll
        for (int nt = 0; nt < 8; nt++)
#pragma unroll
            for (int j = 0; j < 4; j++) acc[mt][nt][j] = 0.f;

#pragma unroll
    for (int ks = 0; ks < 8; ks++) {
        const unsigned int kb = (unsigned int)(ks * 16 + tg * 2) * 2;
        unsigned int a[2][4];
#pragma unroll
        for (int mt = 0; mt < 2; mt++) {
            unsigned int ro = A_OF + (unsigned int)(wr * 32 + mt * 16 + g) * PADB + kb;
            a[mt][0] = *(const unsigned int*)(smem + ro);
            a[mt][1] = *(const unsigned int*)(smem + ro + 8 * PADB);
            a[mt][2] = *(const unsigned int*)(smem + ro + 16);
            a[mt][3] = *(const unsigned int*)(smem + ro + 8 * PADB + 16);
        }
#pragma unroll
        for (int nt = 0; nt < 8; nt++) {
            unsigned int no = B_OF + (unsigned int)(wc * 64 + nt * 8 + g) * PADB + kb;
            unsigned int b[2];
            b[0] = *(const unsigned int*)(smem + no);
            b[1] = *(const unsigned int*)(smem + no + 16);
#pragma unroll
            for (int mt = 0; mt < 2; mt++)
                mma_f16(acc[mt][nt], a[mt], b);
        }
    }

    // ---- scale-free fp8 epilogue: store e4m3(acc * dinv[row])
#pragma unroll
    for (int mt = 0; mt < 2; mt++) {
        int lr = wr * 32 + mt * 16 + g;
        int grow = row0 + lr;
        float d0 = (grow < n) ? g_dinv[grow] : 0.f;
        float d1 = (grow + 8 < n) ? g_dinv[grow + 8] : 0.f;
#pragma unroll
        for (int nt = 0; nt < 8; nt++) {
            int col = wc * 64 + nt * 8 + tg * 2;
            if (grow < n)
                *(unsigned short*)(C8 + (size_t)grow * 128 + col) =
                    f32x2_to_e4m3x2(acc[mt][nt][1] * d0, acc[mt][nt][0] * d0);
            if (grow + 8 < n)
                *(unsigned short*)(C8 + (size_t)(grow + 8) * 128 + col) =
                    f32x2_to_e4m3x2(acc[mt][nt][3] * d1, acc[mt][nt][2] * d1);
        }
    }
}

// ---------------- fused MLP: relu(H+b3)@Wm1+bm1 -> @Wm2+bm2 -> log_softmax --
__global__ void __launch_bounds__(256, 2)
k_mlp(const __half* __restrict__ A16, const float* __restrict__ b3,
      const __half* __restrict__ Wm1f, const float* __restrict__ bm1,
      const __half* __restrict__ Wm2f, const float* __restrict__ bm2,
      float* __restrict__ osm, int n)
{
    extern __shared__ __align__(16) char smem[];
    const unsigned int A_OF = 0;
    const unsigned int B_OF = 128 * PADB;
    const int tid  = threadIdx.x;
    const int wid  = tid >> 5;
    const int lane = tid & 31;
    const int wr   = wid >> 1;
    const int wc   = wid & 1;
    const int row0 = blockIdx.x * 128;
    const int g  = lane >> 2;
    const int tg = lane & 3;

    // ---- A = relu(H16 + b3) tile; B = Wm1 tile
    for (int i = tid; i < 128 * 16; i += 256) {
        int row = i >> 4;
        int unit = i & 15;
        int grow = row0 + row;
        uint4 u = make_uint4(0, 0, 0, 0);
        __half2* hp = (__half2*)&u;
        if (grow < n) u = *(const uint4*)(A16 + (size_t)grow * 128 + unit * 8);
        const float4* b = (const float4*)(b3 + unit * 8);
        float4 b0 = b[0], b1 = b[1];
        float bb[8];
        bb[0] = b0.x; bb[1] = b0.y; bb[2] = b0.z; bb[3] = b0.w;
        bb[4] = b1.x; bb[5] = b1.y; bb[6] = b1.z; bb[7] = b1.w;
#pragma unroll
        for (int j = 0; j < 4; j++) {
            float2 f = __half22float2(hp[j]);
            f.x = fmaxf(f.x + bb[2 * j], 0.f);
            f.y = fmaxf(f.y + bb[2 * j + 1], 0.f);
            hp[j] = __floats2half2_rn(f.x, f.y);
        }
        *(uint4*)(smem + A_OF + (unsigned int)row * PADB + (unsigned int)unit * 16) = u;
    }
    for (int i = tid; i < 128 * 16; i += 256) {
        int row = i >> 4;
        int unit = i & 15;
        *(uint4*)(smem + B_OF + (unsigned int)row * PADB + (unsigned int)unit * 16) =
            ((const uint4*)Wm1f)[row * 16 + unit];
    }
    __syncthreads();

    // ---- MMA 1: T = A @ Wm1 (128 cols)
    float acc[2][8][4];
#pragma unroll
    for (int mt = 0; mt < 2; mt++)
#pragma unroll
        for (int nt = 0; nt < 8; nt++)
#pragma unroll
            for (int j = 0; j < 4; j++) acc[mt][nt][j] = 0.f;

#pragma unroll
    for (int ks = 0; ks < 8; ks++) {
        const unsigned int kb = (unsigned int)(ks * 16 + tg * 2) * 2;
        unsigned int a[2][4];
#pragma unroll
        for (int mt = 0; mt < 2; mt++) {
            unsigned int ro = A_OF + (unsigned int)(wr * 32 + mt * 16 + g) * PADB + kb;
            a[mt][0] = *(const unsigned int*)(smem + ro);
            a[mt][1] = *(const unsigned int*)(smem + ro + 8 * PADB);
            a[mt][2] = *(const unsigned int*)(smem + ro + 16);
            a[mt][3] = *(const unsigned int*)(smem + ro + 8 * PADB + 16);
        }
#pragma unroll
        for (int nt = 0; nt < 8; nt++) {
            unsigned int no = B_OF + (unsigned int)(wc * 64 + nt * 8 + g) * PADB + kb;
            unsigned int b[2];
            b[0] = *(const unsigned int*)(smem + no);
            b[1] = *(const unsigned int*)(smem + no + 16);
#pragma unroll
            for (int mt = 0; mt < 2; mt++)
                mma_f16(acc[mt][nt], a[mt], b);
        }
    }

    __syncthreads();   // all MMA1 reads of A and B complete

    // ---- write T (=acc+bm1, fp16) into A area; load Wm2 into B area
#pragma unroll
    for (int mt = 0; mt < 2; mt++) {
        int lr = wr * 32 + mt * 16 + g;
#pragma unroll
        for (int nt = 0; nt < 8; nt++) {
            int col = wc * 64 + nt * 8 + tg * 2;
            float b0 = bm1[col], b1 = bm1[col + 1];
            *(__half2*)(smem + A_OF + (unsigned int)lr * PADB + col * 2) =
                __floats2half2_rn(acc[mt][nt][0] + b0, acc[mt][nt][1] + b1);
            *(__half2*)(smem + A_OF + (unsigned int)(lr + 8) * PADB + col * 2) =
                __floats2half2_rn(acc[mt][nt][2] + b0, acc[mt][nt][3] + b1);
        }
    }
    for (int i = tid; i < 64 * 16; i += 256) {
        int row = i >> 4;
        int unit = i & 15;
        *(uint4*)(smem + B_OF + (unsigned int)row * PADB + (unsigned int)unit * 16) =
            ((const uint4*)Wm2f)[row * 16 + unit];
    }
    __syncthreads();

    // ---- MMA 2: C = T @ Wm2 (64 cols)
#pragma unroll
    for (int mt = 0; mt < 2; mt++)
#pragma unroll
        for (int nt = 0; nt < 4; nt++)
#pragma unroll
            for (int j = 0; j < 4; j++) acc[mt][nt][j] = 0.f;

#pragma unroll
    for (int ks = 0; ks < 8; ks++) {
        const unsigned int kb = (unsigned int)(ks * 16 + tg * 2) * 2;
        unsigned int a[2][4];
#pragma unroll
        for (int mt = 0; mt < 2; mt++) {
            unsigned int ro = A_OF + (unsigned int)(wr * 32 + mt * 16 + g) * PADB + kb;
            a[mt][0] = *(const unsigned int*)(smem + ro);
            a[mt][1] = *(const unsigned int*)(smem + ro + 8 * PADB);
            a[mt][2] = *(const unsigned int*)(smem + ro + 16);
            a[mt][3] = *(const unsigned int*)(smem + ro + 8 * PADB + 16);
        }
#pragma unroll
        for (int nt = 0; nt < 4; nt++) {
            unsigned int no = B_OF + (unsigned int)(wc * 32 + nt * 8 + g) * PADB + kb;
            unsigned int b[2];
            b[0] = *(const unsigned int*)(smem + no);
            b[1] = *(const unsigned int*)(smem + no + 16);
#pragma unroll
            for (int mt = 0; mt < 2; mt++)
                mma_f16(acc[mt][nt], a[mt], b);
        }
    }

    __syncthreads();   // all MMA2 reads of T complete

    // ---- fused log_softmax (sx reuses A area: 128 rows x 68 floats)
    float* sx = (float*)smem;
#pragma unroll
    for (int mt = 0; mt < 2; mt++) {
        int lr = wr * 32 + mt * 16 + g;
#pragma unroll
        for (int nt = 0; nt < 4; nt++) {
            int col = wc * 32 + nt * 8 + tg * 2;
            float b0 = bm2[col], b1 = bm2[col + 1];
            *(float2*)(sx + lr * 68 + col) =
                make_float2(acc[mt][nt][0] + b0, acc[mt][nt][1] + b1);
            *(float2*)(sx + (lr + 8) * 68 + col) =
                make_float2(acc[mt][nt][2] + b0, acc[mt][nt][3] + b1);
        }
    }
    __syncthreads();
    for (int r = wid * 16; r < wid * 16 + 16; r++) {
        int grow = row0 + r;
        if (grow >= n) break;
        float v0 = sx[r * 68 + lane];
        float v1 = sx[r * 68 + lane + 32];
        float m = fmaxf(v0, v1);
#pragma unroll
        for (int o = 16; o > 0; o >>= 1)
            m = fmaxf(m, __shfl_xor_sync(0xFFFFFFFFu, m, o));
        float s = expf(v0 - m) + expf(v1 - m);
#pragma unroll
        for (int o = 16; o > 0; o >>= 1)
            s += __shfl_xor_sync(0xFFFFFFFFu, s, o);
        float lg = m + logf(s);
        osm[(size_t)grow * 64 + lane]      = v0 - lg;
        osm[(size_t)grow * 64 + lane + 32] = v1 - lg;
    }
}

// ---------------- CSR pull-gather (scale-free fp8 rows) --------------------
// H16[d] = half( dinv[d] * sum_{s in N(d) U {d}} M8[s] )   (M8 pre-scaled)
// Row = 128 fp8 = 16 uint2; lanes 0-15 neighbor j, lanes 16-31 neighbor j+1.
__device__ __forceinline__ void addq8(__half2* a, uint2 u) {
    a[0] = __hadd2(a[0], e4m3x2_to_h2((unsigned short)(u.x)));
    a[1] = __hadd2(a[1], e4m3x2_to_h2((unsigned short)(u.x >> 16)));
    a[2] = __hadd2(a[2], e4m3x2_to_h2((unsigned short)(u.y)));
    a[3] = __hadd2(a[3], e4m3x2_to_h2((unsigned short)(u.y >> 16)));
}

__launch_bounds__(256)
__global__ void k_gather(const uint2* __restrict__ M8,   // row = 16 uint2
                         uint4* __restrict__ H16, int n)  // row = 16 uint4
{
    int warp = (blockIdx.x * blockDim.x + threadIdx.x) >> 5;
    int lane = threadIdx.x & 31;
    if (warp >= n) return;
    int half = lane >> 4;
    int sub  = lane & 15;
    int beg = g_off[warp];
    int total = g_off[warp + 1] - beg + 1;   // +1 self loop (virtual idx 0)

    __half2 acc[4];
#pragma unroll
    for (int k = 0; k < 4; k++) acc[k] = __half2half2(__ushort_as_half(0));

    for (int base = 0; base < total; base += 32) {
        int cnt = total - base;
        if (cnt > 32) cnt = 32;
        int vj = base + lane;
        int idx = 0;
        if (lane < cnt) idx = (vj == 0) ? warp : g_csr[beg + vj - 1];
        int j = 0;
        for (; j + 8 <= cnt; j += 8) {
            int s0 = __shfl_sync(0xFFFFFFFFu, idx, j + half);
            int s1 = __shfl_sync(0xFFFFFFFFu, idx, j + 2 + half);
            int s2 = __shfl_sync(0xFFFFFFFFu, idx, j + 4 + half);
            int s3 = __shfl_sync(0xFFFFFFFFu, idx, j + 6 + half);
            uint2 u0 = M8[(size_t)s0 * 16 + sub];
            uint2 u1 = M8[(size_t)s1 * 16 + sub];
            uint2 u2 = M8[(size_t)s2 * 16 + sub];
            uint2 u3 = M8[(size_t)s3 * 16 + sub];
            addq8(acc, u0);
            addq8(acc, u1);
            addq8(acc, u2);
            addq8(acc, u3);
        }
        if (j + 4 <= cnt) {
            int s0 = __shfl_sync(0xFFFFFFFFu, idx, j + half);
            int s1 = __shfl_sync(0xFFFFFFFFu, idx, j + 2 + half);
            uint2 u0 = M8[(size_t)s0 * 16 + sub];
            uint2 u1 = M8[(size_t)s1 * 16 + sub];
            addq8(acc, u0);
            addq8(acc, u1);
            j += 4;
        }
        if (j + 2 <= cnt) {
            int s = __shfl_sync(0xFFFFFFFFu, idx, j + half);
            uint2 u = M8[(size_t)s * 16 + sub];
            addq8(acc, u);
            j += 2;
        }
        if (j < cnt) {
            int s = __shfl_sync(0xFFFFFFFFu, idx, j);
            if (half == 0) {
                uint2 u = M8[(size_t)s * 16 + sub];
                addq8(acc, u);
            }
        }
    }

    float fa[8];
#pragma unroll
    for (int k = 0; k < 4; k++) {
        float2 t = __half22float2(acc[k]);
        fa[2 * k] = t.x;
        fa[2 * k + 1] = t.y;
    }
#pragma unroll
    for (int k = 0; k < 8; k++)
        fa[k] += __shfl_down_sync(0xFFFFFFFFu, fa[k], 16);

    if (half == 0) {
        float di = g_dinv[warp];
        uint4 o;
        __half2* oh = (__half2*)&o;
#pragma unroll
        for (int i = 0; i < 4; i++)
            oh[i] = __floats2half2_rn(fa[2 * i] * di, fa[2 * i + 1] * di);
        H16[(size_t)warp * 16 + sub] = o;
    }
}

// ---------------- host launcher ---------------------------------------------
extern "C" void kernel_launch(void* const* d_in, const int* in_sizes, int n_in,
                              void* d_out, int out_size)
{
    const float* x   = (const float*)d_in[0];
    const int*   ei  = (const int*)d_in[1];
    const float* W0  = (const float*)d_in[2];
    const float* b0  = (const float*)d_in[3];
    const float* W1  = (const float*)d_in[4];
    const float* b1  = (const float*)d_in[5];
    const float* W2  = (const float*)d_in[6];
    const float* b2  = (const float*)d_in[7];
    const float* W3  = (const float*)d_in[8];
    const float* b3  = (const float*)d_in[9];
    const float* Wm1 = (const float*)d_in[10];
    const float* bm1 = (const float*)d_in[11];
    const float* Wm2 = (const float*)d_in[12];
    const float* bm2 = (const float*)d_in[13];
    float* out = (float*)d_out;

    const int n = in_sizes[0] / DIM;      // 100000
    const int e = in_sizes[1] / 2;        // 1600000
    const int* src = ei;
    const int* dst = ei + e;

    unsigned char* M8 = 0;
    __half* H16 = 0;
    __half* Wf = 0;
    int* Deg = 0;
    cudaGetSymbolAddress((void**)&M8,  g_M8);
    cudaGetSymbolAddress((void**)&H16, g_H16);
    cudaGetSymbolAddress((void**)&Wf,  g_Wf);
    cudaGetSymbolAddress((void**)&Deg, g_deg);

    const int SM128 = 128 * PADB + 128 * PADB;   // 69632
    cudaFuncSetAttribute(k_gemm128, cudaFuncAttributeMaxDynamicSharedMemorySize, SM128);
    cudaFuncSetAttribute(k_mlp,     cudaFuncAttributeMaxDynamicSharedMemorySize, SM128);

    // side stream + fork/join events (created once on the first — correctness —
    // call, outside graph capture; capture records only the event edges)
    static cudaStream_t s2 = 0;
    static cudaEvent_t evF = 0, evD = 0, evB = 0;
    if (!s2) {
        cudaStreamCreateWithFlags(&s2, cudaStreamNonBlocking);
        cudaEventCreateWithFlags(&evF, cudaEventDisableTiming);
        cudaEventCreateWithFlags(&evD, cudaEventDisableTiming);
        cudaEventCreateWithFlags(&evB, cudaEventDisableTiming);
    }

    const int nscanb = (n + SCHUNK - 1) / SCHUNK;
    const int gblocks = (n + 127) / 128;                 // 782
    const int gatherb = (n * 32 + 255) / 256;            // 12500

    // ---- fork: side branch gets weight convert (independent) ----
    cudaEventRecord(evF, 0);
    cudaStreamWaitEvent(s2, evF, 0);
    k_convW_all<<<(WTOT + 255) / 256, 256, 0, s2>>>(W0, W1, W2, W3, Wm1, Wm2);

    // ---- main branch: degrees -> dinv ----
    cudaMemsetAsync(Deg, 0, n * sizeof(int), 0);
    k_count<<<(e + 255) / 256, 256>>>(dst, e);
    k_bsum<<<nscanb, SCHUNK>>>(n);           // also computes dinv
    cudaEventRecord(evD, 0);

    // side branch: layer-0 GEMM (needs Wf slot 0 + dinv + x only)
    cudaStreamWaitEvent(s2, evD, 0);
    k_gemm128<<<gblocks, 256, SM128, s2>>>(x, 0, 0, Wf + 0 * WSLOT, M8, n);
    cudaEventRecord(evB, s2);

    // main branch: CSR build (overlaps with gemm0 on s2)
    k_bscan<<<1, 128>>>(nscanb);
    k_offsets<<<nscanb, SCHUNK>>>(n);        // also preloads g_cur = g_off
    k_fill<<<(e + 255) / 256, 256>>>(src, dst, e);

    // ---- join: gather0 needs CSR (main) + messages (s2) ----
    cudaStreamWaitEvent(0, evB, 0);
    k_gather<<<gatherb, 256>>>((const uint2*)M8, (uint4*)H16, n);

    // ---- layers 1-3 ----
    k_gemm128<<<gblocks, 256, SM128>>>(0, H16, b0, Wf + 1 * WSLOT, M8, n);
    k_gather<<<gatherb, 256>>>((const uint2*)M8, (uint4*)H16, n);

    k_gemm128<<<gblocks, 256, SM128>>>(0, H16, b1, Wf + 2 * WSLOT, M8, n);
    k_gather<<<gatherb, 256>>>((const uint2*)M8, (uint4*)H16, n);

    k_gemm128<<<gblocks, 256, SM128>>>(0, H16, b2, Wf + 3 * WSLOT, M8, n);
    k_gather<<<gatherb, 256>>>((const uint2*)M8, (uint4*)H16, n);

    // ---- fused MLP1 + MLP2 + log_softmax -> out ----
    k_mlp<<<gblocks, 256, SM128>>>(H16, b3, Wf + 4 * WSLOT, bm1,
                                   Wf + 5 * WSLOT, bm2, out, n);
}